// round 5
// baseline (speedup 1.0000x reference)
#include <cuda_runtime.h>
#include <cstdint>

#define B_SZ   512
#define PX     512
#define PH     1024
#define PL     4
#define PVT    512
#define PET    256
#define NG     4096      // 4 gates * PH
#define HID    4096      // PL * PH
#define IN_DIM 2560

#define BM 128
#define BN 128
#define BK 32
#define RS 36            // smem row stride in floats: (36*r + q) mod 32 = (4r+q) -> conflict-free

// Scratch (no allocations allowed)
__device__ float g_Gp[PL * B_SZ * NG];      // gate pre-activations
__device__ float g_hidden[B_SZ * HID];      // concat hidden

__device__ __forceinline__ uint32_t cvt_tf32(float x) {
    uint32_t r; asm("cvt.rna.tf32.f32 %0, %1;" : "=r"(r) : "f"(x)); return r;
}

__device__ __forceinline__ void mma_tf32(float (&d)[4], const uint32_t (&a)[4],
                                         uint32_t b0, uint32_t b1) {
    asm volatile(
        "mma.sync.aligned.m16n8k8.row.col.f32.tf32.tf32.f32 "
        "{%0,%1,%2,%3}, {%4,%5,%6,%7}, {%8,%9}, {%0,%1,%2,%3};\n"
        : "+f"(d[0]), "+f"(d[1]), "+f"(d[2]), "+f"(d[3])
        : "r"(a[0]), "r"(a[1]), "r"(a[2]), "r"(a[3]), "r"(b0), "r"(b1));
}

// MODE 0: partial gates, all layers in parallel (grid.z = layer), K=1536, +bias -> g_Gp
// MODE 1: prev-layer tail for `layer`, K=1024, accumulate into g_Gp
// MODE 2: heads, K=4096, split output layout into d_out
template<int MODE>
__global__ void __launch_bounds__(256, 2)
gemm_tf32(const float* __restrict__ x,
          const float* __restrict__ h_prev,
          const float* __restrict__ Wg,
          const float* __restrict__ bg,
          const float* __restrict__ W_y, const float* __restrict__ b_y,
          const float* __restrict__ W_E, const float* __restrict__ b_E,
          float* __restrict__ d_out,
          int layer)
{
    extern __shared__ float smem[];
    float* As[2] = { smem,                smem + BM * RS };
    float* Bs[2] = { smem + 2 * BM * RS,  smem + 2 * BM * RS + BN * RS };

    const int tid = threadIdx.x;
    const int bm  = blockIdx.y * BM;
    const int bn  = blockIdx.x * BN;
    const int lz  = (MODE == 0) ? blockIdx.z : layer;

    const int Ktot = (MODE == 0) ? (PX + PH) : ((MODE == 1) ? PH : HID);
    const int nT = Ktot / BK;

    // loader mapping: thread -> 4 float4 chunks each for A and B
    const int arow = tid >> 3;          // 0..31, + i*32
    const int kq   = (tid & 7) * 4;     // 0..28

    const int warp = tid >> 5;
    const int lane = tid & 31;
    const int grp  = lane >> 2;
    const int q    = lane & 3;
    const int wm   = (warp & 3) * 32;
    const int wn   = (warp >> 2) * 64;

    float acc[2][8][4];
    #pragma unroll
    for (int i = 0; i < 2; i++)
        #pragma unroll
        for (int j = 0; j < 8; j++)
            #pragma unroll
            for (int v = 0; v < 4; v++) acc[i][j][v] = 0.f;

    float4 ra[4], rb[4];

    // ---- LDG prefetch of tile s into registers ----
    auto prefetch = [&](int s) {
        const int gk = s * BK + kq;
        #pragma unroll
        for (int i = 0; i < 4; i++) {
            const int row = arow + i * 32;
            const float* pa;
            if (MODE == 0) {
                pa = (gk < PX)
                   ? x + (size_t)(bm + row) * PX + gk
                   : h_prev + ((size_t)lz * B_SZ + bm + row) * PH + (gk - PX);
            } else if (MODE == 1) {
                pa = g_hidden + (size_t)(bm + row) * HID + (layer - 1) * PH + gk;
            } else {
                pa = g_hidden + (size_t)(bm + row) * HID + gk;
            }
            ra[i] = *(const float4*)pa;
        }
        #pragma unroll
        for (int i = 0; i < 4; i++) {
            const int gn = bn + arow + i * 32;
            const float* pb;
            if (MODE == 0) {
                pb = Wg + ((size_t)lz * NG + gn) * IN_DIM + gk;
            } else if (MODE == 1) {
                pb = Wg + ((size_t)layer * NG + gn) * IN_DIM + (PX + PH) + gk;
            } else {
                pb = (gn < PVT) ? W_y + (size_t)gn * HID + gk
                                : W_E + (size_t)(gn - PVT) * HID + gk;
            }
            rb[i] = *(const float4*)pb;
        }
    };

    // ---- cvt + STS of register-held tile into buffer `buf` ----
    auto stage = [&](int buf) {
        #pragma unroll
        for (int i = 0; i < 4; i++) {
            float* d = &As[buf][(arow + i * 32) * RS + kq];
            uint32_t* du = (uint32_t*)d;
            du[0] = cvt_tf32(ra[i].x); du[1] = cvt_tf32(ra[i].y);
            du[2] = cvt_tf32(ra[i].z); du[3] = cvt_tf32(ra[i].w);
        }
        #pragma unroll
        for (int i = 0; i < 4; i++) {
            float* d = &Bs[buf][(arow + i * 32) * RS + kq];
            uint32_t* du = (uint32_t*)d;
            du[0] = cvt_tf32(rb[i].x); du[1] = cvt_tf32(rb[i].y);
            du[2] = cvt_tf32(rb[i].z); du[3] = cvt_tf32(rb[i].w);
        }
    };

    // prologue
    prefetch(0);
    stage(0);
    __syncthreads();

    for (int s = 0; s < nT; s++) {
        const int buf = s & 1;
        if (s + 1 < nT) prefetch(s + 1);   // LDG in flight during MMA below

        const float* __restrict__ Ab = As[buf];
        const float* __restrict__ Bb = Bs[buf];
        #pragma unroll
        for (int kk = 0; kk < BK; kk += 8) {
            uint32_t a[2][4];
            #pragma unroll
            for (int im = 0; im < 2; im++) {
                const int r = wm + im * 16 + grp;
                a[im][0] = __float_as_uint(Ab[(r    ) * RS + kk + q    ]);
                a[im][1] = __float_as_uint(Ab[(r + 8) * RS + kk + q    ]);
                a[im][2] = __float_as_uint(Ab[(r    ) * RS + kk + q + 4]);
                a[im][3] = __float_as_uint(Ab[(r + 8) * RS + kk + q + 4]);
            }
            #pragma unroll
            for (int jn = 0; jn < 8; jn++) {
                const int n = wn + jn * 8 + grp;
                const uint32_t b0 = __float_as_uint(Bb[n * RS + kk + q    ]);
                const uint32_t b1 = __float_as_uint(Bb[n * RS + kk + q + 4]);
                mma_tf32(acc[0][jn], a[0], b0, b1);
                mma_tf32(acc[1][jn], a[1], b0, b1);
            }
        }

        if (s + 1 < nT) {
            __syncthreads();            // all warps done reading buf^1 (tile s-1)
            stage(buf ^ 1);             // overwrite with tile s+1
            __syncthreads();            // staged data visible before next MMA
        }
    }

    // ---- epilogue (float2 stores; c0 always even) ----
    #pragma unroll
    for (int im = 0; im < 2; im++) {
        const int r0 = bm + wm + im * 16 + grp;
        #pragma unroll
        for (int jn = 0; jn < 8; jn++) {
            const int c0 = bn + wn + jn * 8 + 2 * q;
            const float2 lo = make_float2(acc[im][jn][0], acc[im][jn][1]);
            const float2 hi = make_float2(acc[im][jn][2], acc[im][jn][3]);
            if (MODE == 0) {
                const float2 b2 = *(const float2*)&bg[(size_t)lz * NG + c0];
                float2* d0 = (float2*)&g_Gp[((size_t)lz * B_SZ + r0    ) * NG + c0];
                float2* d1 = (float2*)&g_Gp[((size_t)lz * B_SZ + r0 + 8) * NG + c0];
                *d0 = make_float2(lo.x + b2.x, lo.y + b2.y);
                *d1 = make_float2(hi.x + b2.x, hi.y + b2.y);
            } else if (MODE == 1) {
                float2* d0 = (float2*)&g_Gp[((size_t)layer * B_SZ + r0    ) * NG + c0];
                float2* d1 = (float2*)&g_Gp[((size_t)layer * B_SZ + r0 + 8) * NG + c0];
                const float2 o0 = *d0, o1 = *d1;
                *d0 = make_float2(lo.x + o0.x, lo.y + o0.y);
                *d1 = make_float2(hi.x + o1.x, hi.y + o1.y);
            } else {
                if (c0 < PVT) {
                    const float2 b2 = *(const float2*)&b_y[c0];
                    float2* d0 = (float2*)&d_out[(size_t)(r0    ) * PVT + c0];
                    float2* d1 = (float2*)&d_out[(size_t)(r0 + 8) * PVT + c0];
                    *d0 = make_float2(lo.x + b2.x, lo.y + b2.y);
                    *d1 = make_float2(hi.x + b2.x, hi.y + b2.y);
                } else {
                    const int c = c0 - PVT;
                    const float2 b2 = *(const float2*)&b_E[c];
                    float* base = d_out + (size_t)B_SZ * PVT;
                    float2* d0 = (float2*)&base[(size_t)(r0    ) * PET + c];
                    float2* d1 = (float2*)&base[(size_t)(r0 + 8) * PET + c];
                    *d0 = make_float2(lo.x + b2.x, lo.y + b2.y);
                    *d1 = make_float2(hi.x + b2.x, hi.y + b2.y);
                }
            }
        }
    }
}

__global__ void lstm_pointwise(const float* __restrict__ c_prev, int layer) {
    const int idx = (blockIdx.x * blockDim.x + threadIdx.x) * 4;
    const int b = idx >> 10;
    const int h = idx & (PH - 1);
    const float* Gb = g_Gp + ((size_t)layer * B_SZ + b) * NG;
    const float4 gi = *(const float4*)&Gb[h];
    const float4 gf = *(const float4*)&Gb[PH + h];
    const float4 go = *(const float4*)&Gb[2 * PH + h];
    const float4 gs = *(const float4*)&Gb[3 * PH + h];
    const float4 cp = *(const float4*)&c_prev[((size_t)layer * B_SZ + b) * PH + h];
    float4 out;
    #define PW(comp) { \
        const float ig = 1.f / (1.f + __expf(-gi.comp)); \
        const float fg = 1.f / (1.f + __expf(-gf.comp)); \
        const float og = 1.f / (1.f + __expf(-go.comp)); \
        const float c  = fg * cp.comp + ig * tanhf(gs.comp); \
        out.comp = og * tanhf(c); }
    PW(x) PW(y) PW(z) PW(w)
    #undef PW
    *(float4*)&g_hidden[(size_t)b * HID + layer * PH + h] = out;
}

extern "C" void kernel_launch(void* const* d_in, const int* in_sizes, int n_in,
                              void* d_out, int out_size) {
    const float* x      = (const float*)d_in[0];
    const float* h_prev = (const float*)d_in[1];
    const float* c_prev = (const float*)d_in[2];
    const float* Wg     = (const float*)d_in[3];
    const float* bg     = (const float*)d_in[4];
    const float* W_y    = (const float*)d_in[5];
    const float* b_y    = (const float*)d_in[6];
    const float* W_E    = (const float*)d_in[7];
    const float* b_E    = (const float*)d_in[8];
    float* out = (float*)d_out;

    const int SMB = 2 * (BM + BN) * RS * (int)sizeof(float);   // 73728
    static bool attr_done = false;
    if (!attr_done) {
        cudaFuncSetAttribute((const void*)gemm_tf32<0>,
                             cudaFuncAttributeMaxDynamicSharedMemorySize, SMB);
        cudaFuncSetAttribute((const void*)gemm_tf32<1>,
                             cudaFuncAttributeMaxDynamicSharedMemorySize, SMB);
        cudaFuncSetAttribute((const void*)gemm_tf32<2>,
                             cudaFuncAttributeMaxDynamicSharedMemorySize, SMB);
        attr_done = true;
    }

    const dim3 blk(256);
    // 1) parallel partial gates for all 4 layers (K=1536, includes bias)
    gemm_tf32<0><<<dim3(NG / BN, B_SZ / BM, PL), blk, SMB>>>(
        x, h_prev, Wg, bg, W_y, b_y, W_E, b_E, out, 0);
    // 2) layer 0: prev_layer is zero -> gates complete
    lstm_pointwise<<<(B_SZ * PH) / 1024, 256>>>(c_prev, 0);
    // 3) layers 1..3: prev-layer tail GEMM (K=1024) + pointwise
    for (int l = 1; l < PL; l++) {
        gemm_tf32<1><<<dim3(NG / BN, B_SZ / BM, 1), blk, SMB>>>(
            x, h_prev, Wg, bg, W_y, b_y, W_E, b_E, out, l);
        lstm_pointwise<<<(B_SZ * PH) / 1024, 256>>>(c_prev, l);
    }
    // 4) fused heads: [512 x 4096] x [4096 x 768]
    gemm_tf32<2><<<dim3((PVT + PET) / BN, B_SZ / BM, 1), blk, SMB>>>(
        x, h_prev, Wg, bg, W_y, b_y, W_E, b_E, out, 0);
}

// round 6
// speedup vs baseline: 1.2055x; 1.2055x over previous
#include <cuda_runtime.h>
#include <cstdint>

#define B_SZ   512
#define PX     512
#define PH     1024
#define PL     4
#define PVT    512
#define PET    256
#define NG     4096      // 4 gates * PH (interleaved col space: col = 4h+g)
#define HID    4096      // PL * PH
#define IN_DIM 2560
#define NHEAD  768       // PVT + PET

#define BM 128
#define BN 128
#define BK 32
#define RS 36            // smem row stride (floats): 4r+q perm -> conflict-free frag LDS

// Scratch (no allocations allowed)
__device__ float g_Gp[PL * B_SZ * NG];      // gate partials (interleaved cols) / MODE2 slices
__device__ float g_hidden[B_SZ * HID];      // concat hidden (natural layout)

__device__ __forceinline__ uint32_t cvt_tf32(float x) {
    uint32_t r; asm("cvt.rna.tf32.f32 %0, %1;" : "=r"(r) : "f"(x)); return r;
}
__device__ __forceinline__ void cp16(uint32_t dst, const void* src) {
    asm volatile("cp.async.cg.shared.global [%0], [%1], 16;" :: "r"(dst), "l"(src));
}
__device__ __forceinline__ void mma_tf32(float (&d)[4], const uint32_t (&a)[4],
                                         uint32_t b0, uint32_t b1) {
    asm volatile(
        "mma.sync.aligned.m16n8k8.row.col.f32.tf32.tf32.f32 "
        "{%0,%1,%2,%3}, {%4,%5,%6,%7}, {%8,%9}, {%0,%1,%2,%3};\n"
        : "+f"(d[0]), "+f"(d[1]), "+f"(d[2]), "+f"(d[3])
        : "r"(a[0]), "r"(a[1]), "r"(a[2]), "r"(a[3]), "r"(b0), "r"(b1));
}
__device__ __forceinline__ float sigm(float x) { return 1.f / (1.f + __expf(-x)); }

// MODE 0: gates, all layers (grid.z=layer), K=1536. lz==0 -> fused pointwise -> g_hidden.
//         lz>0 -> +interleaved bias -> g_Gp.
// MODE 1: prev-layer tail for `layer` (K=1024), + g_Gp partial, fused pointwise -> g_hidden.
// MODE 2: heads K-split (grid.z=kz), K=1024 each, writes slice kz of g_Gp scratch.
template<int MODE>
__global__ void __launch_bounds__(256, 2)
gemm_tf32(const float* __restrict__ x,
          const float* __restrict__ h_prev,
          const float* __restrict__ c_prev,
          const float* __restrict__ Wg,
          const float* __restrict__ bg,
          const float* __restrict__ W_y,
          const float* __restrict__ W_E,
          int layer)
{
    extern __shared__ float smem[];
    float* As[2] = { smem,               smem + BM * RS };
    float* Bs[2] = { smem + 2 * BM * RS, smem + 2 * BM * RS + BN * RS };

    const int tid = threadIdx.x;
    const int bm  = blockIdx.y * BM;
    const int bn  = blockIdx.x * BN;
    const int lz  = (MODE == 0) ? blockIdx.z : layer;          // layer (M0) / kz (M2 via layer)
    const int kz  = (MODE == 2) ? blockIdx.z : 0;

    const int Ktot = (MODE == 0) ? (PX + PH) : PH;             // M1: 1024, M2: 1024 per split
    const int nT = Ktot / BK;

    // loader: thread -> row = tid/2, 64B half-row lkw = (tid&1)*16 floats
    const int lrow = tid >> 1;
    const int lkw  = (tid & 1) * 16;
    const uint32_t sBase = (uint32_t)__cvta_generic_to_shared(smem);
    const uint32_t ldOff = (uint32_t)(lrow * RS + lkw) * 4u;

    const int warp = tid >> 5;
    const int lane = tid & 31;
    const int grp  = lane >> 2;
    const int q    = lane & 3;
    const int wm   = (warp & 3) * 32;
    const int wn   = (warp >> 2) * 64;

    float acc[2][8][4];
    #pragma unroll
    for (int i = 0; i < 2; i++)
        #pragma unroll
        for (int j = 0; j < 8; j++)
            #pragma unroll
            for (int v = 0; v < 4; v++) acc[i][j][v] = 0.f;

    // interleaved weight row for gate GEMMs: col gn -> row (gn&3)*PH + (gn>>2)
    const int gn    = bn + lrow;
    const int wrowI = (gn & 3) * PH + (gn >> 2);

    auto load_stage = [&](int buf, int s) {
        const int gk = s * BK + lkw;                 // 16-float chunk, never straddles PX
        // ---- A ----
        const float* pa;
        if (MODE == 0) {
            pa = (gk < PX)
               ? x + (size_t)(bm + lrow) * PX + gk
               : h_prev + ((size_t)lz * B_SZ + bm + lrow) * PH + (gk - PX);
        } else if (MODE == 1) {
            pa = g_hidden + (size_t)(bm + lrow) * HID + (layer - 1) * PH + gk;
        } else {
            pa = g_hidden + (size_t)(bm + lrow) * HID + kz * PH + gk;
        }
        const uint32_t da = sBase + (uint32_t)buf * (BM * RS * 4) + ldOff;
        cp16(da, pa); cp16(da + 16, pa + 4); cp16(da + 32, pa + 8); cp16(da + 48, pa + 12);
        // ---- B ----
        const float* pb;
        if (MODE == 0) {
            pb = Wg + ((size_t)lz * NG + wrowI) * IN_DIM + gk;
        } else if (MODE == 1) {
            pb = Wg + ((size_t)layer * NG + wrowI) * IN_DIM + (PX + PH) + gk;
        } else {
            pb = (gn < PVT) ? W_y + (size_t)gn * HID + kz * PH + gk
                            : W_E + (size_t)(gn - PVT) * HID + kz * PH + gk;
        }
        const uint32_t db = sBase + (uint32_t)(2 * BM * RS * 4)
                          + (uint32_t)buf * (BN * RS * 4) + ldOff;
        cp16(db, pb); cp16(db + 16, pb + 4); cp16(db + 32, pb + 8); cp16(db + 48, pb + 12);
    };

    // one-time in-place tf32 convert of this thread's own staged chunks
    auto convert = [&](int buf) {
        const int base = lrow * RS + lkw;
        #pragma unroll
        for (int c = 0; c < 4; c++) {
            float* p = As[buf] + base + 4 * c;
            float4 v = *(float4*)p;
            uint32_t u0 = cvt_tf32(v.x), u1 = cvt_tf32(v.y),
                     u2 = cvt_tf32(v.z), u3 = cvt_tf32(v.w);
            uint32_t* up = (uint32_t*)p;
            up[0] = u0; up[1] = u1; up[2] = u2; up[3] = u3;
        }
        #pragma unroll
        for (int c = 0; c < 4; c++) {
            float* p = Bs[buf] + base + 4 * c;
            float4 v = *(float4*)p;
            uint32_t u0 = cvt_tf32(v.x), u1 = cvt_tf32(v.y),
                     u2 = cvt_tf32(v.z), u3 = cvt_tf32(v.w);
            uint32_t* up = (uint32_t*)p;
            up[0] = u0; up[1] = u1; up[2] = u2; up[3] = u3;
        }
    };

    load_stage(0, 0);
    asm volatile("cp.async.commit_group;");

    for (int s = 0; s < nT; s++) {
        const int buf = s & 1;
        if (s + 1 < nT) {
            load_stage(buf ^ 1, s + 1);
            asm volatile("cp.async.commit_group;");
            asm volatile("cp.async.wait_group 1;");
        } else {
            asm volatile("cp.async.wait_group 0;");
        }
        __syncthreads();
        convert(buf);
        __syncthreads();

        const float* __restrict__ Ab = As[buf];
        const float* __restrict__ Bb = Bs[buf];
        #pragma unroll
        for (int kk = 0; kk < BK; kk += 8) {
            uint32_t a[2][4];
            #pragma unroll
            for (int im = 0; im < 2; im++) {
                const int r = wm + im * 16 + grp;
                a[im][0] = __float_as_uint(Ab[(r    ) * RS + kk + q    ]);
                a[im][1] = __float_as_uint(Ab[(r + 8) * RS + kk + q    ]);
                a[im][2] = __float_as_uint(Ab[(r    ) * RS + kk + q + 4]);
                a[im][3] = __float_as_uint(Ab[(r + 8) * RS + kk + q + 4]);
            }
            #pragma unroll
            for (int jn = 0; jn < 8; jn++) {
                const int n = wn + jn * 8 + grp;
                const uint32_t b0 = __float_as_uint(Bb[n * RS + kk + q    ]);
                const uint32_t b1 = __float_as_uint(Bb[n * RS + kk + q + 4]);
                mma_tf32(acc[0][jn], a[0], b0, b1);
                mma_tf32(acc[1][jn], a[1], b0, b1);
            }
        }
        __syncthreads();        // MMA reads done before next stage overwrites / staging
    }

    // ================= epilogues =================
    const bool fused = (MODE == 1) || (MODE == 0 && lz == 0);

    if (fused) {
        // stage acc into smem [128][132], then pointwise with 4-gate groups
        float* st = smem;
        #pragma unroll
        for (int im = 0; im < 2; im++) {
            const int rl = wm + im * 16 + grp;
            #pragma unroll
            for (int jn = 0; jn < 8; jn++) {
                const int cl = wn + jn * 8 + 2 * q;
                *(float2*)&st[rl * 132 + cl]       = make_float2(acc[im][jn][0], acc[im][jn][1]);
                *(float2*)&st[(rl + 8) * 132 + cl] = make_float2(acc[im][jn][2], acc[im][jn][3]);
            }
        }
        __syncthreads();

        const int ll = (MODE == 0) ? 0 : layer;
        const int hc = tid & 31;                 // hidden index within tile
        const int h  = (bn >> 2) + hc;           // within-layer hidden index
        #pragma unroll 1
        for (int pass = 0; pass < 16; pass++) {
            const int row = pass * 8 + (tid >> 5);
            const int gb  = bm + row;
            float4 g = *(const float4*)&st[row * 132 + 4 * hc];
            if (MODE == 0) {                      // lz==0: add bias (interleaved rows)
                g.x += bg[0 * PH + h];
                g.y += bg[1 * PH + h];
                g.z += bg[2 * PH + h];
                g.w += bg[3 * PH + h];
            } else {                              // MODE 1: add partial (bias already in)
                const float4 p = *(const float4*)
                    &g_Gp[((size_t)layer * B_SZ + gb) * NG + bn + 4 * hc];
                g.x += p.x; g.y += p.y; g.z += p.z; g.w += p.w;
            }
            const float ig = sigm(g.x);
            const float fg = sigm(g.y);
            const float og = sigm(g.z);
            const float sg = tanhf(g.w);
            const float cp = c_prev[((size_t)ll * B_SZ + gb) * PH + h];
            const float cn = fg * cp + ig * sg;
            g_hidden[(size_t)gb * HID + ll * PH + h] = og * tanhf(cn);
        }
        return;
    }

    if (MODE == 0) {
        // lz > 0: write partial + interleaved bias to g_Gp
        #pragma unroll
        for (int jn = 0; jn < 8; jn++) {
            const int c0 = bn + wn + jn * 8 + 2 * q;       // even
            const int h  = c0 >> 2;
            const int g0 = c0 & 3;                          // 0 or 2
            const float b0 = bg[(size_t)lz * NG + g0 * PH + h];
            const float b1 = bg[(size_t)lz * NG + (g0 + 1) * PH + h];
            #pragma unroll
            for (int im = 0; im < 2; im++) {
                const int r0 = bm + wm + im * 16 + grp;
                *(float2*)&g_Gp[((size_t)lz * B_SZ + r0    ) * NG + c0]
                    = make_float2(acc[im][jn][0] + b0, acc[im][jn][1] + b1);
                *(float2*)&g_Gp[((size_t)lz * B_SZ + r0 + 8) * NG + c0]
                    = make_float2(acc[im][jn][2] + b0, acc[im][jn][3] + b1);
            }
        }
    } else {
        // MODE 2: write K-slice to scratch (g_Gp), reduced later
        float* sc = g_Gp + (size_t)kz * B_SZ * NHEAD;
        #pragma unroll
        for (int im = 0; im < 2; im++) {
            const int r0 = bm + wm + im * 16 + grp;
            #pragma unroll
            for (int jn = 0; jn < 8; jn++) {
                const int c0 = bn + wn + jn * 8 + 2 * q;
                *(float2*)&sc[(size_t)(r0    ) * NHEAD + c0]
                    = make_float2(acc[im][jn][0], acc[im][jn][1]);
                *(float2*)&sc[(size_t)(r0 + 8) * NHEAD + c0]
                    = make_float2(acc[im][jn][2], acc[im][jn][3]);
            }
        }
    }
}

// sum 4 K-slices + bias -> split d_out layout
__global__ void reduce_heads(const float* __restrict__ b_y,
                             const float* __restrict__ b_E,
                             float* __restrict__ out)
{
    const int idx = (blockIdx.x * blockDim.x + threadIdx.x) * 4;
    const int r = idx / NHEAD;
    const int c = idx % NHEAD;
    float4 s = *(const float4*)&g_Gp[idx];
    #pragma unroll
    for (int kz = 1; kz < 4; kz++) {
        const float4 t = *(const float4*)&g_Gp[(size_t)kz * B_SZ * NHEAD + idx];
        s.x += t.x; s.y += t.y; s.z += t.z; s.w += t.w;
    }
    if (c < PVT) {
        const float4 b = *(const float4*)&b_y[c];
        s.x += b.x; s.y += b.y; s.z += b.z; s.w += b.w;
        *(float4*)&out[(size_t)r * PVT + c] = s;
    } else {
        const int c2 = c - PVT;
        const float4 b = *(const float4*)&b_E[c2];
        s.x += b.x; s.y += b.y; s.z += b.z; s.w += b.w;
        *(float4*)&out[(size_t)B_SZ * PVT + (size_t)r * PET + c2] = s;
    }
}

extern "C" void kernel_launch(void* const* d_in, const int* in_sizes, int n_in,
                              void* d_out, int out_size) {
    const float* x      = (const float*)d_in[0];
    const float* h_prev = (const float*)d_in[1];
    const float* c_prev = (const float*)d_in[2];
    const float* Wg     = (const float*)d_in[3];
    const float* bg     = (const float*)d_in[4];
    const float* W_y    = (const float*)d_in[5];
    const float* b_y    = (const float*)d_in[6];
    const float* W_E    = (const float*)d_in[7];
    const float* b_E    = (const float*)d_in[8];
    float* out = (float*)d_out;

    const int SMB = 2 * (BM + BN) * RS * (int)sizeof(float);   // 73728
    static bool attr_done = false;
    if (!attr_done) {
        cudaFuncSetAttribute((const void*)gemm_tf32<0>,
                             cudaFuncAttributeMaxDynamicSharedMemorySize, SMB);
        cudaFuncSetAttribute((const void*)gemm_tf32<1>,
                             cudaFuncAttributeMaxDynamicSharedMemorySize, SMB);
        cudaFuncSetAttribute((const void*)gemm_tf32<2>,
                             cudaFuncAttributeMaxDynamicSharedMemorySize, SMB);
        attr_done = true;
    }

    const dim3 blk(256);
    // 1) gates for all 4 layers (K=1536); layer 0 fuses pointwise -> g_hidden
    gemm_tf32<0><<<dim3(NG / BN, B_SZ / BM, PL), blk, SMB>>>(
        x, h_prev, c_prev, Wg, bg, W_y, W_E, 0);
    // 2) layers 1..3: prev-layer tail (K=1024) + fused pointwise
    for (int l = 1; l < PL; l++)
        gemm_tf32<1><<<dim3(NG / BN, B_SZ / BM, 1), blk, SMB>>>(
            x, h_prev, c_prev, Wg, bg, W_y, W_E, l);
    // 3) heads, K-split x4 into scratch slices
    gemm_tf32<2><<<dim3(NHEAD / BN, B_SZ / BM, 4), blk, SMB>>>(
        x, h_prev, c_prev, Wg, bg, W_y, W_E, 0);
    // 4) reduce slices + bias -> d_out
    reduce_heads<<<(B_SZ * NHEAD / 4) / 256, 256>>>(b_y, b_E, out);
}

// round 7
// speedup vs baseline: 1.2549x; 1.0410x over previous
#include <cuda_runtime.h>
#include <cstdint>

#define B_SZ   512
#define PX     512
#define PH     1024
#define PL     4
#define PVT    512
#define PET    256
#define NG     4096      // 4 gates * PH (interleaved col space: col = 4h+g)
#define HID    4096      // PL * PH
#define IN_DIM 2560
#define NHEAD  768       // PVT + PET

#define BM 64
#define BN 128
#define BK 32
#define RS 36            // smem row stride (floats): 4r+q perm -> conflict-free frag LDS

// Scratch (no allocations allowed)
__device__ float g_Gp[PL * B_SZ * NG];      // gate partials (interleaved cols) / MODE2 slices
__device__ float g_hidden[B_SZ * HID];      // concat hidden (natural layout)

__device__ __forceinline__ uint32_t cvt_tf32(float x) {
    uint32_t r; asm("cvt.rna.tf32.f32 %0, %1;" : "=r"(r) : "f"(x)); return r;
}
__device__ __forceinline__ void cp16(uint32_t dst, const void* src) {
    asm volatile("cp.async.cg.shared.global [%0], [%1], 16;" :: "r"(dst), "l"(src));
}
__device__ __forceinline__ void mma_tf32(float (&d)[4], const uint32_t (&a)[4],
                                         uint32_t b0, uint32_t b1) {
    asm volatile(
        "mma.sync.aligned.m16n8k8.row.col.f32.tf32.tf32.f32 "
        "{%0,%1,%2,%3}, {%4,%5,%6,%7}, {%8,%9}, {%0,%1,%2,%3};\n"
        : "+f"(d[0]), "+f"(d[1]), "+f"(d[2]), "+f"(d[3])
        : "r"(a[0]), "r"(a[1]), "r"(a[2]), "r"(a[3]), "r"(b0), "r"(b1));
}
__device__ __forceinline__ float sigm(float x) { return 1.f / (1.f + __expf(-x)); }

// smem float offsets
#define AS_OFF(buf) ((buf) * (BM * RS))
#define BS_OFF(buf) (2 * BM * RS + (buf) * (BN * RS))
#define SMEM_FLOATS (2 * BM * RS + 2 * BN * RS)   // 13824 floats = 55296 B

// MODE 0: gates, all layers (grid.z=layer), K=1536. lz==0 -> fused pointwise -> g_hidden.
//         lz>0 -> +interleaved bias -> g_Gp.
// MODE 1: prev-layer tail for `layer` (K=1024), + g_Gp partial, fused pointwise -> g_hidden.
// MODE 2: heads K-split (grid.z=kz), K=1024 each, writes slice kz of g_Gp scratch.
template<int MODE>
__global__ void __launch_bounds__(256, 3)
gemm_tf32(const float* __restrict__ x,
          const float* __restrict__ h_prev,
          const float* __restrict__ c_prev,
          const float* __restrict__ Wg,
          const float* __restrict__ bg,
          const float* __restrict__ W_y,
          const float* __restrict__ W_E,
          int layer)
{
    extern __shared__ float smem[];

    const int tid = threadIdx.x;
    const int bm  = blockIdx.y * BM;
    const int bn  = blockIdx.x * BN;
    const int lz  = (MODE == 0) ? blockIdx.z : layer;
    const int kz  = (MODE == 2) ? blockIdx.z : 0;

    const int Ktot = (MODE == 0) ? (PX + PH) : PH;
    const int nT = Ktot / BK;

    // A loader: 64 rows x 32 floats -> 2 float4/thread
    const int lrowA = tid >> 2;            // 0..63
    const int kqA   = (tid & 3) * 8;       // 0,8,16,24
    // B loader: 128 rows x 32 floats -> 4 float4/thread
    const int lrowB = tid >> 1;            // 0..127
    const int kqB   = (tid & 1) * 16;      // 0,16

    const uint32_t sBase = (uint32_t)__cvta_generic_to_shared(smem);
    const uint32_t ldA = (uint32_t)(lrowA * RS + kqA) * 4u;
    const uint32_t ldB = (uint32_t)(lrowB * RS + kqB) * 4u;

    const int warp = tid >> 5;
    const int lane = tid & 31;
    const int grp  = lane >> 2;
    const int q    = lane & 3;
    const int wm   = (warp & 1) * 32;      // 2 warp rows
    const int wn   = (warp >> 1) * 32;     // 4 warp cols

    float acc[2][4][4];
    #pragma unroll
    for (int i = 0; i < 2; i++)
        #pragma unroll
        for (int j = 0; j < 4; j++)
            #pragma unroll
            for (int v = 0; v < 4; v++) acc[i][j][v] = 0.f;

    // interleaved weight row for gate GEMMs: col gn -> row (gn&3)*PH + (gn>>2)
    const int gnB   = bn + lrowB;
    const int wrowI = (gnB & 3) * PH + (gnB >> 2);

    auto load_stage = [&](int buf, int s) {
        // ---- A (2 x 16B) ----
        const int gka = s * BK + kqA;
        const float* pa;
        if (MODE == 0) {
            pa = (gka < PX)
               ? x + (size_t)(bm + lrowA) * PX + gka
               : h_prev + ((size_t)lz * B_SZ + bm + lrowA) * PH + (gka - PX);
        } else if (MODE == 1) {
            pa = g_hidden + (size_t)(bm + lrowA) * HID + (layer - 1) * PH + gka;
        } else {
            pa = g_hidden + (size_t)(bm + lrowA) * HID + kz * PH + gka;
        }
        const uint32_t da = sBase + (uint32_t)AS_OFF(buf) * 4u + ldA;
        cp16(da, pa); cp16(da + 16, pa + 4);
        // ---- B (4 x 16B) ----
        const int gkb = s * BK + kqB;
        const float* pb;
        if (MODE == 0) {
            pb = Wg + ((size_t)lz * NG + wrowI) * IN_DIM + gkb;
        } else if (MODE == 1) {
            pb = Wg + ((size_t)layer * NG + wrowI) * IN_DIM + (PX + PH) + gkb;
        } else {
            pb = (gnB < PVT) ? W_y + (size_t)gnB * HID + kz * PH + gkb
                             : W_E + (size_t)(gnB - PVT) * HID + kz * PH + gkb;
        }
        const uint32_t db = sBase + (uint32_t)BS_OFF(buf) * 4u + ldB;
        cp16(db, pb); cp16(db + 16, pb + 4); cp16(db + 32, pb + 8); cp16(db + 48, pb + 12);
    };

    // one-time in-place tf32 convert of this thread's own staged chunks
    auto convert = [&](int buf) {
        {
            float* p = smem + AS_OFF(buf) + lrowA * RS + kqA;
            #pragma unroll
            for (int c = 0; c < 2; c++) {
                float4 v = *(float4*)(p + 4 * c);
                uint32_t* up = (uint32_t*)(p + 4 * c);
                up[0] = cvt_tf32(v.x); up[1] = cvt_tf32(v.y);
                up[2] = cvt_tf32(v.z); up[3] = cvt_tf32(v.w);
            }
        }
        {
            float* p = smem + BS_OFF(buf) + lrowB * RS + kqB;
            #pragma unroll
            for (int c = 0; c < 4; c++) {
                float4 v = *(float4*)(p + 4 * c);
                uint32_t* up = (uint32_t*)(p + 4 * c);
                up[0] = cvt_tf32(v.x); up[1] = cvt_tf32(v.y);
                up[2] = cvt_tf32(v.z); up[3] = cvt_tf32(v.w);
            }
        }
    };

    load_stage(0, 0);
    asm volatile("cp.async.commit_group;");

    for (int s = 0; s < nT; s++) {
        const int buf = s & 1;
        if (s + 1 < nT) {
            load_stage(buf ^ 1, s + 1);
            asm volatile("cp.async.commit_group;");
            asm volatile("cp.async.wait_group 1;");
        } else {
            asm volatile("cp.async.wait_group 0;");
        }
        __syncthreads();
        convert(buf);
        __syncthreads();

        const float* __restrict__ Ab = smem + AS_OFF(buf);
        const float* __restrict__ Bb = smem + BS_OFF(buf);
        #pragma unroll
        for (int kk = 0; kk < BK; kk += 8) {
            uint32_t a[2][4];
            #pragma unroll
            for (int im = 0; im < 2; im++) {
                const int r = wm + im * 16 + grp;
                a[im][0] = __float_as_uint(Ab[(r    ) * RS + kk + q    ]);
                a[im][1] = __float_as_uint(Ab[(r + 8) * RS + kk + q    ]);
                a[im][2] = __float_as_uint(Ab[(r    ) * RS + kk + q + 4]);
                a[im][3] = __float_as_uint(Ab[(r + 8) * RS + kk + q + 4]);
            }
            #pragma unroll
            for (int jn = 0; jn < 4; jn++) {
                const int n = wn + jn * 8 + grp;
                const uint32_t b0 = __float_as_uint(Bb[n * RS + kk + q    ]);
                const uint32_t b1 = __float_as_uint(Bb[n * RS + kk + q + 4]);
                mma_tf32(acc[0][jn], a[0], b0, b1);
                mma_tf32(acc[1][jn], a[1], b0, b1);
            }
        }
        __syncthreads();
    }

    // ================= epilogues =================
    const bool fused = (MODE == 1) || (MODE == 0 && lz == 0);

    if (fused) {
        // stage acc into smem [64][132], then pointwise with 4-gate groups
        float* st = smem;
        #pragma unroll
        for (int im = 0; im < 2; im++) {
            const int rl = wm + im * 16 + grp;
            #pragma unroll
            for (int jn = 0; jn < 4; jn++) {
                const int cl = wn + jn * 8 + 2 * q;
                *(float2*)&st[rl * 132 + cl]       = make_float2(acc[im][jn][0], acc[im][jn][1]);
                *(float2*)&st[(rl + 8) * 132 + cl] = make_float2(acc[im][jn][2], acc[im][jn][3]);
            }
        }
        __syncthreads();

        const int ll = (MODE == 0) ? 0 : layer;
        const int hc = tid & 31;
        const int h  = (bn >> 2) + hc;
        #pragma unroll 1
        for (int pass = 0; pass < 8; pass++) {
            const int row = pass * 8 + (tid >> 5);
            const int gb  = bm + row;
            float4 g = *(const float4*)&st[row * 132 + 4 * hc];
            if (MODE == 0) {
                g.x += bg[0 * PH + h];
                g.y += bg[1 * PH + h];
                g.z += bg[2 * PH + h];
                g.w += bg[3 * PH + h];
            } else {
                const float4 p = *(const float4*)
                    &g_Gp[((size_t)layer * B_SZ + gb) * NG + bn + 4 * hc];
                g.x += p.x; g.y += p.y; g.z += p.z; g.w += p.w;
            }
            const float ig = sigm(g.x);
            const float fg = sigm(g.y);
            const float og = sigm(g.z);
            const float sg = tanhf(g.w);
            const float cp = c_prev[((size_t)ll * B_SZ + gb) * PH + h];
            const float cn = fg * cp + ig * sg;
            g_hidden[(size_t)gb * HID + ll * PH + h] = og * tanhf(cn);
        }
        return;
    }

    if (MODE == 0) {
        // lz > 0: write partial + interleaved bias to g_Gp
        #pragma unroll
        for (int jn = 0; jn < 4; jn++) {
            const int c0 = bn + wn + jn * 8 + 2 * q;        // even
            const int h  = c0 >> 2;
            const int g0 = c0 & 3;
            const float b0 = bg[(size_t)lz * NG + g0 * PH + h];
            const float b1 = bg[(size_t)lz * NG + (g0 + 1) * PH + h];
            #pragma unroll
            for (int im = 0; im < 2; im++) {
                const int r0 = bm + wm + im * 16 + grp;
                *(float2*)&g_Gp[((size_t)lz * B_SZ + r0    ) * NG + c0]
                    = make_float2(acc[im][jn][0] + b0, acc[im][jn][1] + b1);
                *(float2*)&g_Gp[((size_t)lz * B_SZ + r0 + 8) * NG + c0]
                    = make_float2(acc[im][jn][2] + b0, acc[im][jn][3] + b1);
            }
        }
    } else {
        // MODE 2: write K-slice to scratch (g_Gp), reduced later
        float* sc = g_Gp + (size_t)kz * B_SZ * NHEAD;
        #pragma unroll
        for (int im = 0; im < 2; im++) {
            const int r0 = bm + wm + im * 16 + grp;
            #pragma unroll
            for (int jn = 0; jn < 4; jn++) {
                const int c0 = bn + wn + jn * 8 + 2 * q;
                *(float2*)&sc[(size_t)(r0    ) * NHEAD + c0]
                    = make_float2(acc[im][jn][0], acc[im][jn][1]);
                *(float2*)&sc[(size_t)(r0 + 8) * NHEAD + c0]
                    = make_float2(acc[im][jn][2], acc[im][jn][3]);
            }
        }
    }
}

// sum 4 K-slices + bias -> split d_out layout
__global__ void reduce_heads(const float* __restrict__ b_y,
                             const float* __restrict__ b_E,
                             float* __restrict__ out)
{
    const int idx = (blockIdx.x * blockDim.x + threadIdx.x) * 4;
    const int r = idx / NHEAD;
    const int c = idx % NHEAD;
    float4 s = *(const float4*)&g_Gp[idx];
    #pragma unroll
    for (int kzi = 1; kzi < 4; kzi++) {
        const float4 t = *(const float4*)&g_Gp[(size_t)kzi * B_SZ * NHEAD + idx];
        s.x += t.x; s.y += t.y; s.z += t.z; s.w += t.w;
    }
    if (c < PVT) {
        const float4 b = *(const float4*)&b_y[c];
        s.x += b.x; s.y += b.y; s.z += b.z; s.w += b.w;
        *(float4*)&out[(size_t)r * PVT + c] = s;
    } else {
        const int c2 = c - PVT;
        const float4 b = *(const float4*)&b_E[c2];
        s.x += b.x; s.y += b.y; s.z += b.z; s.w += b.w;
        *(float4*)&out[(size_t)B_SZ * PVT + (size_t)r * PET + c2] = s;
    }
}

extern "C" void kernel_launch(void* const* d_in, const int* in_sizes, int n_in,
                              void* d_out, int out_size) {
    const float* x      = (const float*)d_in[0];
    const float* h_prev = (const float*)d_in[1];
    const float* c_prev = (const float*)d_in[2];
    const float* Wg     = (const float*)d_in[3];
    const float* bg     = (const float*)d_in[4];
    const float* W_y    = (const float*)d_in[5];
    const float* b_y    = (const float*)d_in[6];
    const float* W_E    = (const float*)d_in[7];
    const float* b_E    = (const float*)d_in[8];
    float* out = (float*)d_out;

    const int SMB = SMEM_FLOATS * (int)sizeof(float);   // 55296
    static bool attr_done = false;
    if (!attr_done) {
        cudaFuncSetAttribute((const void*)gemm_tf32<0>,
                             cudaFuncAttributeMaxDynamicSharedMemorySize, SMB);
        cudaFuncSetAttribute((const void*)gemm_tf32<1>,
                             cudaFuncAttributeMaxDynamicSharedMemorySize, SMB);
        cudaFuncSetAttribute((const void*)gemm_tf32<2>,
                             cudaFuncAttributeMaxDynamicSharedMemorySize, SMB);
        attr_done = true;
    }

    const dim3 blk(256);
    // 1) gates for all 4 layers (K=1536); layer 0 fuses pointwise -> g_hidden
    gemm_tf32<0><<<dim3(NG / BN, B_SZ / BM, PL), blk, SMB>>>(
        x, h_prev, c_prev, Wg, bg, W_y, W_E, 0);
    // 2) layers 1..3: prev-layer tail (K=1024) + fused pointwise
    for (int l = 1; l < PL; l++)
        gemm_tf32<1><<<dim3(NG / BN, B_SZ / BM, 1), blk, SMB>>>(
            x, h_prev, c_prev, Wg, bg, W_y, W_E, l);
    // 3) heads, K-split x4 into scratch slices
    gemm_tf32<2><<<dim3(NHEAD / BN, B_SZ / BM, 4), blk, SMB>>>(
        x, h_prev, c_prev, Wg, bg, W_y, W_E, 0);
    // 4) reduce slices + bias -> d_out
    reduce_heads<<<(B_SZ * NHEAD / 4) / 256, 256>>>(b_y, b_E, out);
}

// round 8
// speedup vs baseline: 1.2721x; 1.0137x over previous
#include <cuda_runtime.h>
#include <cstdint>

#define B_SZ   512
#define PX     512
#define PH     1024
#define PL     4
#define PVT    512
#define PET    256
#define NG     4096      // 4 gates * PH (interleaved col space: col = 4h+g)
#define HID    4096      // PL * PH
#define IN_DIM 2560
#define NHEAD  768       // PVT + PET

#define BM 64
#define BN 128
#define BK 16
#define RS 20            // row stride: (20r+q) mod 32 distinct over frag lanes -> conflict-free
#define NSTG 3

// Scratch (no allocations allowed)
__device__ float g_Gp[PL * B_SZ * NG];      // MODE0 partials (interleaved) / MODE2 slices
__device__ float g_Tp[2 * B_SZ * NG];       // tail split-K slices
__device__ float g_hidden[B_SZ * HID];      // concat hidden

__device__ __forceinline__ uint32_t cvt_tf32(float x) {
    uint32_t r; asm("cvt.rna.tf32.f32 %0, %1;" : "=r"(r) : "f"(x)); return r;
}
__device__ __forceinline__ void cp16(uint32_t dst, const void* src) {
    asm volatile("cp.async.cg.shared.global [%0], [%1], 16;" :: "r"(dst), "l"(src));
}
__device__ __forceinline__ void mma_tf32(float (&d)[4], const uint32_t (&a)[4],
                                         uint32_t b0, uint32_t b1) {
    asm volatile(
        "mma.sync.aligned.m16n8k8.row.col.f32.tf32.tf32.f32 "
        "{%0,%1,%2,%3}, {%4,%5,%6,%7}, {%8,%9}, {%0,%1,%2,%3};\n"
        : "+f"(d[0]), "+f"(d[1]), "+f"(d[2]), "+f"(d[3])
        : "r"(a[0]), "r"(a[1]), "r"(a[2]), "r"(a[3]), "r"(b0), "r"(b1));
}
__device__ __forceinline__ float sigm(float x) { return 1.f / (1.f + __expf(-x)); }

#define AS_OFF(buf) ((buf) * ((BM + BN) * RS))
#define BS_OFF(buf) ((buf) * ((BM + BN) * RS) + BM * RS)
#define SMEM_FLOATS (NSTG * (BM + BN) * RS)          // 11520 floats = 46080 B

// MODE 0: gates, all layers (grid.z=layer), K=1536. lz==0 -> fused pointwise -> g_hidden,
//         lz>0 -> +interleaved bias -> g_Gp.
// MODE 1: tail for `layer`, split-K (grid.z=kz in 0..1), K=512 each -> g_Tp slice.
// MODE 2: heads, split-K (grid.z=kz in 0..7), K=512 each -> g_Gp slice (scratch).
template<int MODE>
__global__ void __launch_bounds__(256, 3)
gemm_tf32(const float* __restrict__ x,
          const float* __restrict__ h_prev,
          const float* __restrict__ c_prev,
          const float* __restrict__ Wg,
          const float* __restrict__ bg,
          const float* __restrict__ W_y,
          const float* __restrict__ W_E,
          int layer)
{
    extern __shared__ float smem[];

    const int tid = threadIdx.x;
    const int bm  = blockIdx.y * BM;
    const int bn  = blockIdx.x * BN;
    const int lz  = (MODE == 0) ? blockIdx.z : layer;
    const int kz  = (MODE == 0) ? 0 : blockIdx.z;

    const int Ktot = (MODE == 0) ? (PX + PH) : 512;
    const int nT = Ktot / BK;                 // 96 / 32 / 32

    // A loader: 64x16 floats -> 1 float4/thread
    const int lrowA = tid >> 2;               // 0..63
    const int kqA   = (tid & 3) * 4;          // 0,4,8,12
    // B loader: 128x16 floats -> 2 float4/thread
    const int lrowB = tid >> 1;               // 0..127
    const int kqB   = (tid & 1) * 8;          // 0,8  (chunks at kqB, kqB+4)

    const uint32_t sBase = (uint32_t)__cvta_generic_to_shared(smem);
    const uint32_t ldA = (uint32_t)(lrowA * RS + kqA) * 4u;
    const uint32_t ldB = (uint32_t)(lrowB * RS + kqB) * 4u;

    const int warp = tid >> 5;
    const int lane = tid & 31;
    const int grp  = lane >> 2;
    const int q    = lane & 3;
    const int wm   = (warp & 1) * 32;
    const int wn   = (warp >> 1) * 32;

    float acc[2][4][4];
    #pragma unroll
    for (int i = 0; i < 2; i++)
        #pragma unroll
        for (int j = 0; j < 4; j++)
            #pragma unroll
            for (int v = 0; v < 4; v++) acc[i][j][v] = 0.f;

    const int gnB   = bn + lrowB;
    const int wrowI = (gnB & 3) * PH + (gnB >> 2);   // interleaved gate-weight row

    auto load_stage = [&](int buf, int s) {
        // ---- A (1 x 16B) ----
        const int gka = s * BK + kqA;
        const float* pa;
        if (MODE == 0) {
            pa = (gka < PX)
               ? x + (size_t)(bm + lrowA) * PX + gka
               : h_prev + ((size_t)lz * B_SZ + bm + lrowA) * PH + (gka - PX);
        } else if (MODE == 1) {
            pa = g_hidden + (size_t)(bm + lrowA) * HID + (layer - 1) * PH + kz * 512 + gka;
        } else {
            pa = g_hidden + (size_t)(bm + lrowA) * HID + kz * 512 + gka;
        }
        cp16(sBase + (uint32_t)AS_OFF(buf) * 4u + ldA, pa);
        // ---- B (2 x 16B) ----
        const int gkb = s * BK + kqB;
        const float* pb;
        if (MODE == 0) {
            pb = Wg + ((size_t)lz * NG + wrowI) * IN_DIM + gkb;
        } else if (MODE == 1) {
            pb = Wg + ((size_t)layer * NG + wrowI) * IN_DIM + (PX + PH) + kz * 512 + gkb;
        } else {
            pb = (gnB < PVT) ? W_y + (size_t)gnB * HID + kz * 512 + gkb
                             : W_E + (size_t)(gnB - PVT) * HID + kz * 512 + gkb;
        }
        const uint32_t db = sBase + (uint32_t)BS_OFF(buf) * 4u + ldB;
        cp16(db, pb); cp16(db + 16, pb + 4);
    };

    // convert this thread's OWN staged chunks (valid after its wait_group, pre-barrier)
    auto convert = [&](int buf) {
        {
            float* p = smem + AS_OFF(buf) + lrowA * RS + kqA;
            float4 v = *(float4*)p;
            uint32_t* up = (uint32_t*)p;
            up[0] = cvt_tf32(v.x); up[1] = cvt_tf32(v.y);
            up[2] = cvt_tf32(v.z); up[3] = cvt_tf32(v.w);
        }
        float* pb0 = smem + BS_OFF(buf) + lrowB * RS + kqB;
        #pragma unroll
        for (int c = 0; c < 2; c++) {
            float4 v = *(float4*)(pb0 + 4 * c);
            uint32_t* up = (uint32_t*)(pb0 + 4 * c);
            up[0] = cvt_tf32(v.x); up[1] = cvt_tf32(v.y);
            up[2] = cvt_tf32(v.z); up[3] = cvt_tf32(v.w);
        }
    };

    // prologue: stages 0 and 1 in flight; convert 0
    load_stage(0, 0);
    asm volatile("cp.async.commit_group;");
    load_stage(1, 1);
    asm volatile("cp.async.commit_group;");
    asm volatile("cp.async.wait_group 1;");
    convert(0);
    __syncthreads();

    for (int s = 0; s < nT; s++) {
        const int buf = s % 3;
        if (s + 2 < nT) {
            load_stage((s + 2) % 3, s + 2);
            asm volatile("cp.async.commit_group;");
        }

        // ---- MMA on stage s (converted + published) ----
        const float* __restrict__ Ab = smem + AS_OFF(buf);
        const float* __restrict__ Bb = smem + BS_OFF(buf);
        #pragma unroll
        for (int kk = 0; kk < BK; kk += 8) {
            uint32_t a[2][4];
            #pragma unroll
            for (int im = 0; im < 2; im++) {
                const int r = wm + im * 16 + grp;
                a[im][0] = __float_as_uint(Ab[(r    ) * RS + kk + q    ]);
                a[im][1] = __float_as_uint(Ab[(r + 8) * RS + kk + q    ]);
                a[im][2] = __float_as_uint(Ab[(r    ) * RS + kk + q + 4]);
                a[im][3] = __float_as_uint(Ab[(r + 8) * RS + kk + q + 4]);
            }
            #pragma unroll
            for (int jn = 0; jn < 4; jn++) {
                const int n = wn + jn * 8 + grp;
                const uint32_t b0 = __float_as_uint(Bb[n * RS + kk + q    ]);
                const uint32_t b1 = __float_as_uint(Bb[n * RS + kk + q + 4]);
                mma_tf32(acc[0][jn], a[0], b0, b1);
                mma_tf32(acc[1][jn], a[1], b0, b1);
            }
        }

        // ---- convert stage s+1 (own chunks), publish with single barrier ----
        if (s + 1 < nT) {
            if (s + 2 < nT) { asm volatile("cp.async.wait_group 1;"); }
            else            { asm volatile("cp.async.wait_group 0;"); }
            convert((s + 1) % 3);
        }
        __syncthreads();
    }

    // ================= epilogues =================
    if (MODE == 0 && lz == 0) {
        // fused LSTM pointwise for layer 0 (full K in this CTA)
        float* st = smem;
        #pragma unroll
        for (int im = 0; im < 2; im++) {
            const int rl = wm + im * 16 + grp;
            #pragma unroll
            for (int jn = 0; jn < 4; jn++) {
                const int cl = wn + jn * 8 + 2 * q;
                *(float2*)&st[rl * 132 + cl]       = make_float2(acc[im][jn][0], acc[im][jn][1]);
                *(float2*)&st[(rl + 8) * 132 + cl] = make_float2(acc[im][jn][2], acc[im][jn][3]);
            }
        }
        __syncthreads();

        const int hc = tid & 31;
        const int h  = (bn >> 2) + hc;
        #pragma unroll 1
        for (int pass = 0; pass < 8; pass++) {
            const int row = pass * 8 + (tid >> 5);
            const int gb  = bm + row;
            float4 g = *(const float4*)&st[row * 132 + 4 * hc];
            g.x += bg[0 * PH + h];
            g.y += bg[1 * PH + h];
            g.z += bg[2 * PH + h];
            g.w += bg[3 * PH + h];
            const float ig = sigm(g.x);
            const float fg = sigm(g.y);
            const float og = sigm(g.z);
            const float sg = tanhf(g.w);
            const float cp = c_prev[(size_t)gb * PH + h];
            const float cn = fg * cp + ig * sg;
            g_hidden[(size_t)gb * HID + h] = og * tanhf(cn);
        }
        return;
    }

    if (MODE == 0) {
        // lz > 0: partial + interleaved bias -> g_Gp
        #pragma unroll
        for (int jn = 0; jn < 4; jn++) {
            const int c0 = bn + wn + jn * 8 + 2 * q;
            const int h  = c0 >> 2;
            const int g0 = c0 & 3;
            const float b0 = bg[(size_t)lz * NG + g0 * PH + h];
            const float b1 = bg[(size_t)lz * NG + (g0 + 1) * PH + h];
            #pragma unroll
            for (int im = 0; im < 2; im++) {
                const int r0 = bm + wm + im * 16 + grp;
                *(float2*)&g_Gp[((size_t)lz * B_SZ + r0    ) * NG + c0]
                    = make_float2(acc[im][jn][0] + b0, acc[im][jn][1] + b1);
                *(float2*)&g_Gp[((size_t)lz * B_SZ + r0 + 8) * NG + c0]
                    = make_float2(acc[im][jn][2] + b0, acc[im][jn][3] + b1);
            }
        }
    } else if (MODE == 1) {
        float* sc = g_Tp + (size_t)kz * B_SZ * NG;
        #pragma unroll
        for (int im = 0; im < 2; im++) {
            const int r0 = bm + wm + im * 16 + grp;
            #pragma unroll
            for (int jn = 0; jn < 4; jn++) {
                const int c0 = bn + wn + jn * 8 + 2 * q;
                *(float2*)&sc[(size_t)(r0    ) * NG + c0]
                    = make_float2(acc[im][jn][0], acc[im][jn][1]);
                *(float2*)&sc[(size_t)(r0 + 8) * NG + c0]
                    = make_float2(acc[im][jn][2], acc[im][jn][3]);
            }
        }
    } else {
        float* sc = g_Gp + (size_t)kz * B_SZ * NHEAD;
        #pragma unroll
        for (int im = 0; im < 2; im++) {
            const int r0 = bm + wm + im * 16 + grp;
            #pragma unroll
            for (int jn = 0; jn < 4; jn++) {
                const int c0 = bn + wn + jn * 8 + 2 * q;
                *(float2*)&sc[(size_t)(r0    ) * NHEAD + c0]
                    = make_float2(acc[im][jn][0], acc[im][jn][1]);
                *(float2*)&sc[(size_t)(r0 + 8) * NHEAD + c0]
                    = make_float2(acc[im][jn][2], acc[im][jn][3]);
            }
        }
    }
}

// LSTM pointwise for layers 1..3: g = g_Gp[layer] (partial+bias) + tail slices 0,1
__global__ void lstm_tail_pointwise(const float* __restrict__ c_prev, int layer) {
    const int idx = blockIdx.x * blockDim.x + threadIdx.x;   // one (b, h) each
    const int b = idx >> 10;
    const int h = idx & (PH - 1);
    const size_t off = (size_t)b * NG + 4 * h;
    float4 g = *(const float4*)&g_Gp[(size_t)layer * B_SZ * NG + off];
    const float4 t0 = *(const float4*)&g_Tp[off];
    const float4 t1 = *(const float4*)&g_Tp[(size_t)B_SZ * NG + off];
    g.x += t0.x + t1.x; g.y += t0.y + t1.y;
    g.z += t0.z + t1.z; g.w += t0.w + t1.w;
    const float ig = sigm(g.x);
    const float fg = sigm(g.y);
    const float og = sigm(g.z);
    const float sg = tanhf(g.w);
    const float cp = c_prev[((size_t)layer * B_SZ + b) * PH + h];
    const float cn = fg * cp + ig * sg;
    g_hidden[(size_t)b * HID + layer * PH + h] = og * tanhf(cn);
}

// sum 8 K-slices + bias -> split d_out layout
__global__ void reduce_heads(const float* __restrict__ b_y,
                             const float* __restrict__ b_E,
                             float* __restrict__ out)
{
    const int idx = (blockIdx.x * blockDim.x + threadIdx.x) * 4;
    const int r = idx / NHEAD;
    const int c = idx % NHEAD;
    float4 s = *(const float4*)&g_Gp[idx];
    #pragma unroll
    for (int kzi = 1; kzi < 8; kzi++) {
        const float4 t = *(const float4*)&g_Gp[(size_t)kzi * B_SZ * NHEAD + idx];
        s.x += t.x; s.y += t.y; s.z += t.z; s.w += t.w;
    }
    if (c < PVT) {
        const float4 b = *(const float4*)&b_y[c];
        s.x += b.x; s.y += b.y; s.z += b.z; s.w += b.w;
        *(float4*)&out[(size_t)r * PVT + c] = s;
    } else {
        const int c2 = c - PVT;
        const float4 b = *(const float4*)&b_E[c2];
        s.x += b.x; s.y += b.y; s.z += b.z; s.w += b.w;
        *(float4*)&out[(size_t)B_SZ * PVT + (size_t)r * PET + c2] = s;
    }
}

extern "C" void kernel_launch(void* const* d_in, const int* in_sizes, int n_in,
                              void* d_out, int out_size) {
    const float* x      = (const float*)d_in[0];
    const float* h_prev = (const float*)d_in[1];
    const float* c_prev = (const float*)d_in[2];
    const float* Wg     = (const float*)d_in[3];
    const float* bg     = (const float*)d_in[4];
    const float* W_y    = (const float*)d_in[5];
    const float* b_y    = (const float*)d_in[6];
    const float* W_E    = (const float*)d_in[7];
    const float* b_E    = (const float*)d_in[8];
    float* out = (float*)d_out;

    const int SMB = SMEM_FLOATS * (int)sizeof(float);   // 46080 <= 48KB default
    const dim3 blk(256);

    // 1) gates for all 4 layers (K=1536); layer 0 fuses pointwise -> g_hidden
    gemm_tf32<0><<<dim3(NG / BN, B_SZ / BM, PL), blk, SMB>>>(
        x, h_prev, c_prev, Wg, bg, W_y, W_E, 0);
    // 2) layers 1..3: tail split-K x2 (K=512 each) -> slices, then fused pointwise
    for (int l = 1; l < PL; l++) {
        gemm_tf32<1><<<dim3(NG / BN, B_SZ / BM, 2), blk, SMB>>>(
            x, h_prev, c_prev, Wg, bg, W_y, W_E, l);
        lstm_tail_pointwise<<<(B_SZ * PH) / 256, 256>>>(c_prev, l);
    }
    // 3) heads, split-K x8 (K=512 each) -> g_Gp scratch slices
    gemm_tf32<2><<<dim3(NHEAD / BN, B_SZ / BM, 8), blk, SMB>>>(
        x, h_prev, c_prev, Wg, bg, W_y, W_E, 0);
    // 4) reduce slices + bias -> d_out
    reduce_heads<<<(B_SZ * NHEAD / 4) / 256, 256>>>(b_y, b_E, out);
}

// round 9
// speedup vs baseline: 1.5451x; 1.2146x over previous
#include <cuda_runtime.h>
#include <cstdint>

#define B_SZ   512
#define PX     512
#define PH     1024
#define PL     4
#define PVT    512
#define PET    256
#define NG     4096      // 4 gates * PH (interleaved col space: col = 4h+g)
#define HID    4096      // PL * PH
#define IN_DIM 2560
#define NHEAD  768       // PVT + PET

#define BM 128
#define BN 128
#define BK 16
#define RS 20            // smem row stride (floats), conflict-free for frag LDS
#define KS_TAIL 4        // tail split-K factor (K=256 each)
#define KS_HEAD 8        // heads split-K factor (K=512 each)

// Scratch (no allocations allowed)
__device__ float g_Gp[PL * B_SZ * NG];        // MODE0 partials (interleaved) / head slices
__device__ float g_Tp[KS_TAIL * B_SZ * NG];   // tail split-K slices
__device__ float g_hidden[B_SZ * HID];        // concat hidden

__device__ __forceinline__ uint32_t cvt_tf32(float x) {
    uint32_t r; asm("cvt.rna.tf32.f32 %0, %1;" : "=r"(r) : "f"(x)); return r;
}
__device__ __forceinline__ void cp16(uint32_t dst, const void* src) {
    asm volatile("cp.async.cg.shared.global [%0], [%1], 16;" :: "r"(dst), "l"(src));
}
__device__ __forceinline__ void mma_tf32(float (&d)[4], const uint32_t (&a)[4],
                                         uint32_t b0, uint32_t b1) {
    asm volatile(
        "mma.sync.aligned.m16n8k8.row.col.f32.tf32.tf32.f32 "
        "{%0,%1,%2,%3}, {%4,%5,%6,%7}, {%8,%9}, {%0,%1,%2,%3};\n"
        : "+f"(d[0]), "+f"(d[1]), "+f"(d[2]), "+f"(d[3])
        : "r"(a[0]), "r"(a[1]), "r"(a[2]), "r"(a[3]), "r"(b0), "r"(b1));
}
__device__ __forceinline__ float sigm(float x) { return 1.f / (1.f + __expf(-x)); }

// MODE 0: gates, all layers (grid.z=layer), K=1536. lz==0 -> fused pointwise -> g_hidden,
//         lz>0 -> +interleaved bias -> g_Gp.
// MODE 1: tail for `layer`, split-K (grid.z=kz in 0..3), K=256 each -> g_Tp slice.
// MODE 2: heads, split-K (grid.z=kz in 0..7), K=512 each -> g_Gp slice (scratch).
template<int MODE>
__global__ void __launch_bounds__(256, 2)
gemm_tf32(const float* __restrict__ x,
          const float* __restrict__ h_prev,
          const float* __restrict__ c_prev,
          const float* __restrict__ Wg,
          const float* __restrict__ bg,
          const float* __restrict__ W_y,
          const float* __restrict__ W_E,
          int layer)
{
    extern __shared__ float smem[];
    float* As[2] = { smem,               smem + BM * RS };
    float* Bs[2] = { smem + 2 * BM * RS, smem + 2 * BM * RS + BN * RS };

    const int tid = threadIdx.x;
    const int bm  = blockIdx.y * BM;
    const int bn  = blockIdx.x * BN;
    const int lz  = (MODE == 0) ? blockIdx.z : layer;
    const int kz  = (MODE == 0) ? 0 : blockIdx.z;

    const int Ktot = (MODE == 0) ? (PX + PH) : ((MODE == 1) ? PH / KS_TAIL : HID / KS_HEAD);
    const int nT = Ktot / BK;                 // 96 / 16 / 32

    // loader: thread -> row = tid/2, 8-float half-row lkw = (tid&1)*8
    const int lrow = tid >> 1;
    const int lkw  = (tid & 1) * 8;
    const uint32_t sBase = (uint32_t)__cvta_generic_to_shared(smem);
    const uint32_t ldOff = (uint32_t)(lrow * RS + lkw) * 4u;

    const int warp = tid >> 5;
    const int lane = tid & 31;
    const int grp  = lane >> 2;
    const int q    = lane & 3;
    const int wm   = (warp & 3) * 32;
    const int wn   = (warp >> 2) * 64;

    float acc[2][8][4];
    #pragma unroll
    for (int i = 0; i < 2; i++)
        #pragma unroll
        for (int j = 0; j < 8; j++)
            #pragma unroll
            for (int v = 0; v < 4; v++) acc[i][j][v] = 0.f;

    // interleaved weight row for gate GEMMs: col gn -> row (gn&3)*PH + (gn>>2)
    const int gn    = bn + lrow;
    const int wrowI = (gn & 3) * PH + (gn >> 2);

    auto load_stage = [&](int buf, int s) {
        const int gk = s * BK + lkw;
        // ---- A (2 x 16B) ----
        const float* pa;
        if (MODE == 0) {
            pa = (gk < PX)
               ? x + (size_t)(bm + lrow) * PX + gk
               : h_prev + ((size_t)lz * B_SZ + bm + lrow) * PH + (gk - PX);
        } else if (MODE == 1) {
            pa = g_hidden + (size_t)(bm + lrow) * HID + (layer - 1) * PH
               + kz * (PH / KS_TAIL) + gk;
        } else {
            pa = g_hidden + (size_t)(bm + lrow) * HID + kz * (HID / KS_HEAD) + gk;
        }
        const uint32_t da = sBase + (uint32_t)buf * (BM * RS * 4) + ldOff;
        cp16(da, pa); cp16(da + 16, pa + 4);
        // ---- B (2 x 16B) ----
        const float* pb;
        if (MODE == 0) {
            pb = Wg + ((size_t)lz * NG + wrowI) * IN_DIM + gk;
        } else if (MODE == 1) {
            pb = Wg + ((size_t)layer * NG + wrowI) * IN_DIM + (PX + PH)
               + kz * (PH / KS_TAIL) + gk;
        } else {
            pb = (gn < PVT) ? W_y + (size_t)gn * HID + kz * (HID / KS_HEAD) + gk
                            : W_E + (size_t)(gn - PVT) * HID + kz * (HID / KS_HEAD) + gk;
        }
        const uint32_t db = sBase + (uint32_t)(2 * BM * RS * 4)
                          + (uint32_t)buf * (BN * RS * 4) + ldOff;
        cp16(db, pb); cp16(db + 16, pb + 4);
    };

    load_stage(0, 0);
    asm volatile("cp.async.commit_group;");

    for (int s = 0; s < nT; s++) {
        const int buf = s & 1;
        if (s + 1 < nT) {
            load_stage(buf ^ 1, s + 1);
            asm volatile("cp.async.commit_group;");
            asm volatile("cp.async.wait_group 1;");
        } else {
            asm volatile("cp.async.wait_group 0;");
        }
        __syncthreads();

        const float* __restrict__ Ab = As[buf];
        const float* __restrict__ Bb = Bs[buf];
        #pragma unroll
        for (int kk = 0; kk < BK; kk += 8) {
            uint32_t a[2][4];
            #pragma unroll
            for (int im = 0; im < 2; im++) {
                const int r = wm + im * 16 + grp;
                a[im][0] = cvt_tf32(Ab[(r    ) * RS + kk + q    ]);
                a[im][1] = cvt_tf32(Ab[(r + 8) * RS + kk + q    ]);
                a[im][2] = cvt_tf32(Ab[(r    ) * RS + kk + q + 4]);
                a[im][3] = cvt_tf32(Ab[(r + 8) * RS + kk + q + 4]);
            }
            #pragma unroll
            for (int jn = 0; jn < 8; jn++) {
                const int n = wn + jn * 8 + grp;
                const uint32_t b0 = cvt_tf32(Bb[n * RS + kk + q    ]);
                const uint32_t b1 = cvt_tf32(Bb[n * RS + kk + q + 4]);
                mma_tf32(acc[0][jn], a[0], b0, b1);
                mma_tf32(acc[1][jn], a[1], b0, b1);
            }
        }
        __syncthreads();
    }

    // ================= epilogues =================
    if (MODE == 0 && lz == 0) {
        // fused LSTM pointwise for layer 0 (full K in this CTA)
        float* st = smem;                          // 128 x 132 floats = 67584 B
        #pragma unroll
        for (int im = 0; im < 2; im++) {
            const int rl = wm + im * 16 + grp;
            #pragma unroll
            for (int jn = 0; jn < 8; jn++) {
                const int cl = wn + jn * 8 + 2 * q;
                *(float2*)&st[rl * 132 + cl]       = make_float2(acc[im][jn][0], acc[im][jn][1]);
                *(float2*)&st[(rl + 8) * 132 + cl] = make_float2(acc[im][jn][2], acc[im][jn][3]);
            }
        }
        __syncthreads();

        const int hc = tid & 31;
        const int h  = (bn >> 2) + hc;
        #pragma unroll 1
        for (int pass = 0; pass < 16; pass++) {
            const int row = pass * 8 + (tid >> 5);
            const int gb  = bm + row;
            float4 g = *(const float4*)&st[row * 132 + 4 * hc];
            g.x += bg[0 * PH + h];
            g.y += bg[1 * PH + h];
            g.z += bg[2 * PH + h];
            g.w += bg[3 * PH + h];
            const float ig = sigm(g.x);
            const float fg = sigm(g.y);
            const float og = sigm(g.z);
            const float sg = tanhf(g.w);
            const float cp = c_prev[(size_t)gb * PH + h];
            const float cn = fg * cp + ig * sg;
            g_hidden[(size_t)gb * HID + h] = og * tanhf(cn);
        }
        return;
    }

    if (MODE == 0) {
        // lz > 0: partial + interleaved bias -> g_Gp
        #pragma unroll
        for (int jn = 0; jn < 8; jn++) {
            const int c0 = bn + wn + jn * 8 + 2 * q;
            const int h  = c0 >> 2;
            const int g0 = c0 & 3;
            const float b0 = bg[(size_t)lz * NG + g0 * PH + h];
            const float b1 = bg[(size_t)lz * NG + (g0 + 1) * PH + h];
            #pragma unroll
            for (int im = 0; im < 2; im++) {
                const int r0 = bm + wm + im * 16 + grp;
                *(float2*)&g_Gp[((size_t)lz * B_SZ + r0    ) * NG + c0]
                    = make_float2(acc[im][jn][0] + b0, acc[im][jn][1] + b1);
                *(float2*)&g_Gp[((size_t)lz * B_SZ + r0 + 8) * NG + c0]
                    = make_float2(acc[im][jn][2] + b0, acc[im][jn][3] + b1);
            }
        }
    } else if (MODE == 1) {
        float* sc = g_Tp + (size_t)kz * B_SZ * NG;
        #pragma unroll
        for (int im = 0; im < 2; im++) {
            const int r0 = bm + wm + im * 16 + grp;
            #pragma unroll
            for (int jn = 0; jn < 8; jn++) {
                const int c0 = bn + wn + jn * 8 + 2 * q;
                *(float2*)&sc[(size_t)(r0    ) * NG + c0]
                    = make_float2(acc[im][jn][0], acc[im][jn][1]);
                *(float2*)&sc[(size_t)(r0 + 8) * NG + c0]
                    = make_float2(acc[im][jn][2], acc[im][jn][3]);
            }
        }
    } else {
        float* sc = g_Gp + (size_t)kz * B_SZ * NHEAD;
        #pragma unroll
        for (int im = 0; im < 2; im++) {
            const int r0 = bm + wm + im * 16 + grp;
            #pragma unroll
            for (int jn = 0; jn < 8; jn++) {
                const int c0 = bn + wn + jn * 8 + 2 * q;
                *(float2*)&sc[(size_t)(r0    ) * NHEAD + c0]
                    = make_float2(acc[im][jn][0], acc[im][jn][1]);
                *(float2*)&sc[(size_t)(r0 + 8) * NHEAD + c0]
                    = make_float2(acc[im][jn][2], acc[im][jn][3]);
            }
        }
    }
}

// LSTM pointwise for layers 1..3: g = g_Gp[layer] (partial+bias) + 4 tail slices
__global__ void lstm_tail_pointwise(const float* __restrict__ c_prev, int layer) {
    const int idx = blockIdx.x * blockDim.x + threadIdx.x;   // one (b, h) each
    const int b = idx >> 10;
    const int h = idx & (PH - 1);
    const size_t off = (size_t)b * NG + 4 * h;
    float4 g = *(const float4*)&g_Gp[(size_t)layer * B_SZ * NG + off];
    #pragma unroll
    for (int kzi = 0; kzi < KS_TAIL; kzi++) {
        const float4 t = *(const float4*)&g_Tp[(size_t)kzi * B_SZ * NG + off];
        g.x += t.x; g.y += t.y; g.z += t.z; g.w += t.w;
    }
    const float ig = sigm(g.x);
    const float fg = sigm(g.y);
    const float og = sigm(g.z);
    const float sg = tanhf(g.w);
    const float cp = c_prev[((size_t)layer * B_SZ + b) * PH + h];
    const float cn = fg * cp + ig * sg;
    g_hidden[(size_t)b * HID + layer * PH + h] = og * tanhf(cn);
}

// sum 8 head K-slices + bias -> split d_out layout
__global__ void reduce_heads(const float* __restrict__ b_y,
                             const float* __restrict__ b_E,
                             float* __restrict__ out)
{
    const int idx = (blockIdx.x * blockDim.x + threadIdx.x) * 4;
    const int r = idx / NHEAD;
    const int c = idx % NHEAD;
    float4 s = *(const float4*)&g_Gp[idx];
    #pragma unroll
    for (int kzi = 1; kzi < KS_HEAD; kzi++) {
        const float4 t = *(const float4*)&g_Gp[(size_t)kzi * B_SZ * NHEAD + idx];
        s.x += t.x; s.y += t.y; s.z += t.z; s.w += t.w;
    }
    if (c < PVT) {
        const float4 b = *(const float4*)&b_y[c];
        s.x += b.x; s.y += b.y; s.z += b.z; s.w += b.w;
        *(float4*)&out[(size_t)r * PVT + c] = s;
    } else {
        const int c2 = c - PVT;
        const float4 b = *(const float4*)&b_E[c2];
        s.x += b.x; s.y += b.y; s.z += b.z; s.w += b.w;
        *(float4*)&out[(size_t)B_SZ * PVT + (size_t)r * PET + c2] = s;
    }
}

extern "C" void kernel_launch(void* const* d_in, const int* in_sizes, int n_in,
                              void* d_out, int out_size) {
    const float* x      = (const float*)d_in[0];
    const float* h_prev = (const float*)d_in[1];
    const float* c_prev = (const float*)d_in[2];
    const float* Wg     = (const float*)d_in[3];
    const float* bg     = (const float*)d_in[4];
    const float* W_y    = (const float*)d_in[5];
    const float* b_y    = (const float*)d_in[6];
    const float* W_E    = (const float*)d_in[7];
    const float* b_E    = (const float*)d_in[8];
    float* out = (float*)d_out;

    // smem: max(GEMM pipeline 40960 B, epilogue staging 128*132*4 = 67584 B)
    const int SMB = 128 * 132 * (int)sizeof(float);   // 67584
    static bool attr_done = false;
    if (!attr_done) {
        cudaFuncSetAttribute((const void*)gemm_tf32<0>,
                             cudaFuncAttributeMaxDynamicSharedMemorySize, SMB);
        cudaFuncSetAttribute((const void*)gemm_tf32<1>,
                             cudaFuncAttributeMaxDynamicSharedMemorySize, SMB);
        cudaFuncSetAttribute((const void*)gemm_tf32<2>,
                             cudaFuncAttributeMaxDynamicSharedMemorySize, SMB);
        attr_done = true;
    }

    const dim3 blk(256);
    // 1) gates for all 4 layers (K=1536); layer 0 fuses pointwise -> g_hidden
    gemm_tf32<0><<<dim3(NG / BN, B_SZ / BM, PL), blk, SMB>>>(
        x, h_prev, c_prev, Wg, bg, W_y, W_E, 0);
    // 2) layers 1..3: tail split-K x4 (K=256 each) -> slices, then fused pointwise
    for (int l = 1; l < PL; l++) {
        gemm_tf32<1><<<dim3(NG / BN, B_SZ / BM, KS_TAIL), blk, SMB>>>(
            x, h_prev, c_prev, Wg, bg, W_y, W_E, l);
        lstm_tail_pointwise<<<(B_SZ * PH) / 256, 256>>>(c_prev, l);
    }
    // 3) heads, split-K x8 (K=512 each) -> g_Gp scratch slices
    gemm_tf32<2><<<dim3(NHEAD / BN, B_SZ / BM, KS_HEAD), blk, SMB>>>(
        x, h_prev, c_prev, Wg, bg, W_y, W_E, 0);
    // 4) reduce slices + bias -> d_out
    reduce_heads<<<(B_SZ * NHEAD / 4) / 256, 256>>>(b_y, b_E, out);
}

// round 10
// speedup vs baseline: 1.5898x; 1.0289x over previous
#include <cuda_runtime.h>
#include <cstdint>

#define B_SZ   512
#define PX     512
#define PH     1024
#define PL     4
#define PVT    512
#define PET    256
#define NG     4096      // 4 gates * PH (interleaved col space: col = 4h+g)
#define HID    4096      // PL * PH
#define IN_DIM 2560
#define IN0    1536      // PX + PH
#define NHEAD  768       // PVT + PET

#define BM 128
#define BN 128
#define BK 16
#define RS 20            // smem row stride (floats), conflict-free for frag LDS
#define KS_TAIL 4        // tail split-K factor (K=256 each)
#define KS_HEAD 8        // heads split-K factor (K=512 each)

// Scratch (no allocations allowed)
__device__ float g_Gp[PL * B_SZ * NG];        // MODE0 partials (interleaved) / head slices
__device__ float g_Tp[KS_TAIL * B_SZ * NG];   // tail split-K slices
__device__ float g_hidden[B_SZ * HID];        // concat hidden (tf32-rounded)
__device__ float g_Wt[PL * NG * IN_DIM];      // tf32-rounded gate weights (orig layout)
__device__ float g_WHt[NHEAD * HID];          // tf32-rounded [W_y; W_E]
__device__ float g_A0[PL * B_SZ * IN0];       // tf32-rounded [x | h_prev[l]] per layer

__device__ __forceinline__ uint32_t cvt_tf32(float x) {
    uint32_t r; asm("cvt.rna.tf32.f32 %0, %1;" : "=r"(r) : "f"(x)); return r;
}
__device__ __forceinline__ float cvtf(float x) { return __uint_as_float(cvt_tf32(x)); }
__device__ __forceinline__ void cp16(uint32_t dst, const void* src) {
    asm volatile("cp.async.cg.shared.global [%0], [%1], 16;" :: "r"(dst), "l"(src));
}
__device__ __forceinline__ void mma_tf32(float (&d)[4], const uint32_t (&a)[4],
                                         uint32_t b0, uint32_t b1) {
    asm volatile(
        "mma.sync.aligned.m16n8k8.row.col.f32.tf32.tf32.f32 "
        "{%0,%1,%2,%3}, {%4,%5,%6,%7}, {%8,%9}, {%0,%1,%2,%3};\n"
        : "+f"(d[0]), "+f"(d[1]), "+f"(d[2]), "+f"(d[3])
        : "r"(a[0]), "r"(a[1]), "r"(a[2]), "r"(a[3]), "r"(b0), "r"(b1));
}
__device__ __forceinline__ float sigm(float x) { return 1.f / (1.f + __expf(-x)); }

// ---- transform kernels (launch-time tf32 rounding) ----
__global__ void prep_cvt(const float* __restrict__ src, float* __restrict__ dst, int n4) {
    const int i = blockIdx.x * blockDim.x + threadIdx.x;
    if (i >= n4) return;
    const float4 v = ((const float4*)src)[i];
    ((float4*)dst)[i] = make_float4(cvtf(v.x), cvtf(v.y), cvtf(v.z), cvtf(v.w));
}
__global__ void prep_A0(const float* __restrict__ x, const float* __restrict__ h_prev) {
    const int i = blockIdx.x * blockDim.x + threadIdx.x;   // float4 index
    const int c  = (i * 4) % IN0;
    const int lb = (i * 4) / IN0;          // l * B_SZ + b
    const float4 v = (c < PX)
        ? *(const float4*)&x[(size_t)(lb % B_SZ) * PX + c]
        : *(const float4*)&h_prev[(size_t)lb * PH + (c - PX) - (size_t)(lb % B_SZ) * PH
                                  + (size_t)(lb % B_SZ) * PH];   // see note below
    // simpler exact addressing:
    // h_prev[((l*B_SZ)+b)*PH + (c-PX)] where lb = l*B_SZ+b
    ((float4*)g_A0)[i] = make_float4(cvtf(v.x), cvtf(v.y), cvtf(v.z), cvtf(v.w));
}

// MODE 0: gates, all layers (grid.z=layer), K=1536. lz==0 -> fused pointwise -> g_hidden,
//         lz>0 -> +interleaved bias -> g_Gp.
// MODE 1: tail for `layer`, split-K (grid.z=kz in 0..3), K=256 each -> g_Tp slice.
// MODE 2: heads, split-K (grid.z=kz in 0..7), K=512 each -> g_Gp slice (scratch).
template<int MODE>
__global__ void __launch_bounds__(256, 2)
gemm_tf32(const float* __restrict__ c_prev,
          const float* __restrict__ bg,
          int layer)
{
    extern __shared__ float smem[];

    const int tid = threadIdx.x;
    const int bm  = blockIdx.y * BM;
    const int bn  = blockIdx.x * BN;
    const int lz  = (MODE == 0) ? blockIdx.z : layer;
    const int kz  = (MODE == 0) ? 0 : blockIdx.z;

    const int Ktot = (MODE == 0) ? IN0 : ((MODE == 1) ? PH / KS_TAIL : HID / KS_HEAD);
    const int nT = Ktot / BK;                 // 96 / 16 / 32

    // loader: thread -> row = tid/2, 8-float half-row lkw = (tid&1)*8
    const int lrow = tid >> 1;
    const int lkw  = (tid & 1) * 8;
    const uint32_t sBase = (uint32_t)__cvta_generic_to_shared(smem);
    const uint32_t ldOff = (uint32_t)(lrow * RS + lkw) * 4u;

    const int warp = tid >> 5;
    const int lane = tid & 31;
    const int grp  = lane >> 2;
    const int q    = lane & 3;
    const int wm   = (warp & 3) * 32;
    const int wn   = (warp >> 2) * 64;

    float acc[2][8][4];
    #pragma unroll
    for (int i = 0; i < 2; i++)
        #pragma unroll
        for (int j = 0; j < 8; j++)
            #pragma unroll
            for (int v = 0; v < 4; v++) acc[i][j][v] = 0.f;

    // interleaved weight row for gate GEMMs: col gn -> row (gn&3)*PH + (gn>>2)
    const int gn    = bn + lrow;
    const int wrowI = (gn & 3) * PH + (gn >> 2);

    // invariant source row pointers
    const float* pa_row;
    const float* pb_row;
    if (MODE == 0) {
        pa_row = g_A0 + ((size_t)lz * B_SZ + bm + lrow) * IN0;
        pb_row = g_Wt + ((size_t)lz * NG + wrowI) * IN_DIM;
    } else if (MODE == 1) {
        pa_row = g_hidden + (size_t)(bm + lrow) * HID + (layer - 1) * PH
               + kz * (PH / KS_TAIL);
        pb_row = g_Wt + ((size_t)layer * NG + wrowI) * IN_DIM + IN0
               + kz * (PH / KS_TAIL);
    } else {
        pa_row = g_hidden + (size_t)(bm + lrow) * HID + kz * (HID / KS_HEAD);
        pb_row = g_WHt + (size_t)gn * HID + kz * (HID / KS_HEAD);
    }

    auto load_stage = [&](int buf, int s) {
        const int gk = s * BK + lkw;
        const uint32_t da = sBase + (uint32_t)buf * ((BM + BN) * RS * 4) + ldOff;
        cp16(da, pa_row + gk); cp16(da + 16, pa_row + gk + 4);
        const uint32_t db = da + (uint32_t)(BM * RS * 4);
        cp16(db, pb_row + gk); cp16(db + 16, pb_row + gk + 4);
    };

    load_stage(0, 0);
    asm volatile("cp.async.commit_group;");
    load_stage(1, 1);
    asm volatile("cp.async.commit_group;");

    for (int s = 0; s < nT; s++) {
        const int buf = s % 3;
        if (s + 1 < nT) { asm volatile("cp.async.wait_group 1;"); }
        else            { asm volatile("cp.async.wait_group 0;"); }
        __syncthreads();                       // stage s visible; MMA(s-1) done everywhere
        if (s + 2 < nT) {
            load_stage((s + 2) % 3, s + 2);    // overwrites stage s-1's buffer (safe)
            asm volatile("cp.async.commit_group;");
        }

        const float* __restrict__ Ab = smem + buf * ((BM + BN) * RS);
        const float* __restrict__ Bb = Ab + BM * RS;
        #pragma unroll
        for (int kk = 0; kk < BK; kk += 8) {
            uint32_t a[2][4];
            #pragma unroll
            for (int im = 0; im < 2; im++) {
                const int r = wm + im * 16 + grp;
                a[im][0] = __float_as_uint(Ab[(r    ) * RS + kk + q    ]);
                a[im][1] = __float_as_uint(Ab[(r + 8) * RS + kk + q    ]);
                a[im][2] = __float_as_uint(Ab[(r    ) * RS + kk + q + 4]);
                a[im][3] = __float_as_uint(Ab[(r + 8) * RS + kk + q + 4]);
            }
            #pragma unroll
            for (int jn = 0; jn < 8; jn++) {
                const int n = wn + jn * 8 + grp;
                const uint32_t b0 = __float_as_uint(Bb[n * RS + kk + q    ]);
                const uint32_t b1 = __float_as_uint(Bb[n * RS + kk + q + 4]);
                mma_tf32(acc[0][jn], a[0], b0, b1);
                mma_tf32(acc[1][jn], a[1], b0, b1);
            }
        }
    }

    // ================= epilogues =================
    if (MODE == 0 && lz == 0) {
        // fused LSTM pointwise for layer 0 (full K in this CTA)
        __syncthreads();                       // all warps done with smem tiles
        float* st = smem;                      // 128 x 132 floats
        #pragma unroll
        for (int im = 0; im < 2; im++) {
            const int rl = wm + im * 16 + grp;
            #pragma unroll
            for (int jn = 0; jn < 8; jn++) {
                const int cl = wn + jn * 8 + 2 * q;
                *(float2*)&st[rl * 132 + cl]       = make_float2(acc[im][jn][0], acc[im][jn][1]);
                *(float2*)&st[(rl + 8) * 132 + cl] = make_float2(acc[im][jn][2], acc[im][jn][3]);
            }
        }
        __syncthreads();

        const int hc = tid & 31;
        const int h  = (bn >> 2) + hc;
        #pragma unroll 1
        for (int pass = 0; pass < 16; pass++) {
            const int row = pass * 8 + (tid >> 5);
            const int gb  = bm + row;
            float4 g = *(const float4*)&st[row * 132 + 4 * hc];
            g.x += bg[0 * PH + h];
            g.y += bg[1 * PH + h];
            g.z += bg[2 * PH + h];
            g.w += bg[3 * PH + h];
            const float ig = sigm(g.x);
            const float fg = sigm(g.y);
            const float og = sigm(g.z);
            const float sg = tanhf(g.w);
            const float cp = c_prev[(size_t)gb * PH + h];
            const float cn = fg * cp + ig * sg;
            g_hidden[(size_t)gb * HID + h] = cvtf(og * tanhf(cn));
        }
        return;
    }

    if (MODE == 0) {
        // lz > 0: partial + interleaved bias -> g_Gp
        #pragma unroll
        for (int jn = 0; jn < 8; jn++) {
            const int c0 = bn + wn + jn * 8 + 2 * q;
            const int h  = c0 >> 2;
            const int g0 = c0 & 3;
            const float b0 = bg[(size_t)lz * NG + g0 * PH + h];
            const float b1 = bg[(size_t)lz * NG + (g0 + 1) * PH + h];
            #pragma unroll
            for (int im = 0; im < 2; im++) {
                const int r0 = bm + wm + im * 16 + grp;
                *(float2*)&g_Gp[((size_t)lz * B_SZ + r0    ) * NG + c0]
                    = make_float2(acc[im][jn][0] + b0, acc[im][jn][1] + b1);
                *(float2*)&g_Gp[((size_t)lz * B_SZ + r0 + 8) * NG + c0]
                    = make_float2(acc[im][jn][2] + b0, acc[im][jn][3] + b1);
            }
        }
    } else if (MODE == 1) {
        float* sc = g_Tp + (size_t)kz * B_SZ * NG;
        #pragma unroll
        for (int im = 0; im < 2; im++) {
            const int r0 = bm + wm + im * 16 + grp;
            #pragma unroll
            for (int jn = 0; jn < 8; jn++) {
                const int c0 = bn + wn + jn * 8 + 2 * q;
                *(float2*)&sc[(size_t)(r0    ) * NG + c0]
                    = make_float2(acc[im][jn][0], acc[im][jn][1]);
                *(float2*)&sc[(size_t)(r0 + 8) * NG + c0]
                    = make_float2(acc[im][jn][2], acc[im][jn][3]);
            }
        }
    } else {
        float* sc = g_Gp + (size_t)kz * B_SZ * NHEAD;
        #pragma unroll
        for (int im = 0; im < 2; im++) {
            const int r0 = bm + wm + im * 16 + grp;
            #pragma unroll
            for (int jn = 0; jn < 8; jn++) {
                const int c0 = bn + wn + jn * 8 + 2 * q;
                *(float2*)&sc[(size_t)(r0    ) * NHEAD + c0]
                    = make_float2(acc[im][jn][0], acc[im][jn][1]);
                *(float2*)&sc[(size_t)(r0 + 8) * NHEAD + c0]
                    = make_float2(acc[im][jn][2], acc[im][jn][3]);
            }
        }
    }
}

// LSTM pointwise for layers 1..3: g = g_Gp[layer] (partial+bias) + 4 tail slices
__global__ void lstm_tail_pointwise(const float* __restrict__ c_prev, int layer) {
    const int idx = blockIdx.x * blockDim.x + threadIdx.x;   // one (b, h) each
    const int b = idx >> 10;
    const int h = idx & (PH - 1);
    const size_t off = (size_t)b * NG + 4 * h;
    float4 g = *(const float4*)&g_Gp[(size_t)layer * B_SZ * NG + off];
    #pragma unroll
    for (int kzi = 0; kzi < KS_TAIL; kzi++) {
        const float4 t = *(const float4*)&g_Tp[(size_t)kzi * B_SZ * NG + off];
        g.x += t.x; g.y += t.y; g.z += t.z; g.w += t.w;
    }
    const float ig = sigm(g.x);
    const float fg = sigm(g.y);
    const float og = sigm(g.z);
    const float sg = tanhf(g.w);
    const float cp = c_prev[((size_t)layer * B_SZ + b) * PH + h];
    const float cn = fg * cp + ig * sg;
    g_hidden[(size_t)b * HID + layer * PH + h] = cvtf(og * tanhf(cn));
}

// sum 8 head K-slices + bias -> split d_out layout
__global__ void reduce_heads(const float* __restrict__ b_y,
                             const float* __restrict__ b_E,
                             float* __restrict__ out)
{
    const int idx = (blockIdx.x * blockDim.x + threadIdx.x) * 4;
    const int r = idx / NHEAD;
    const int c = idx % NHEAD;
    float4 s = *(const float4*)&g_Gp[idx];
    #pragma unroll
    for (int kzi = 1; kzi < KS_HEAD; kzi++) {
        const float4 t = *(const float4*)&g_Gp[(size_t)kzi * B_SZ * NHEAD + idx];
        s.x += t.x; s.y += t.y; s.z += t.z; s.w += t.w;
    }
    if (c < PVT) {
        const float4 b = *(const float4*)&b_y[c];
        s.x += b.x; s.y += b.y; s.z += b.z; s.w += b.w;
        *(float4*)&out[(size_t)r * PVT + c] = s;
    } else {
        const int c2 = c - PVT;
        const float4 b = *(const float4*)&b_E[c2];
        s.x += b.x; s.y += b.y; s.z += b.z; s.w += b.w;
        *(float4*)&out[(size_t)B_SZ * PVT + (size_t)r * PET + c2] = s;
    }
}

extern "C" void kernel_launch(void* const* d_in, const int* in_sizes, int n_in,
                              void* d_out, int out_size) {
    const float* x      = (const float*)d_in[0];
    const float* h_prev = (const float*)d_in[1];
    const float* c_prev = (const float*)d_in[2];
    const float* Wg     = (const float*)d_in[3];
    const float* bg     = (const float*)d_in[4];
    const float* W_y    = (const float*)d_in[5];
    const float* b_y    = (const float*)d_in[6];
    const float* W_E    = (const float*)d_in[7];
    const float* b_E    = (const float*)d_in[8];
    float* out = (float*)d_out;

    // resolve device-scratch addresses for transform kernels
    float *dWt, *dWHt;
    cudaGetSymbolAddress((void**)&dWt,  g_Wt);
    cudaGetSymbolAddress((void**)&dWHt, g_WHt);

    // smem: max(GEMM pipeline 3*256*20*4 = 61440, epilogue staging 128*132*4 = 67584)
    const int SMB = 128 * 132 * (int)sizeof(float);   // 67584
    static bool attr_done = false;
    if (!attr_done) {
        cudaFuncSetAttribute((const void*)gemm_tf32<0>,
                             cudaFuncAttributeMaxDynamicSharedMemorySize, SMB);
        cudaFuncSetAttribute((const void*)gemm_tf32<1>,
                             cudaFuncAttributeMaxDynamicSharedMemorySize, SMB);
        cudaFuncSetAttribute((const void*)gemm_tf32<2>,
                             cudaFuncAttributeMaxDynamicSharedMemorySize, SMB);
        attr_done = true;
    }

    // 0) tf32 pre-rounding transforms
    prep_cvt<<<(PL * NG * IN_DIM / 4 + 255) / 256, 256>>>(Wg, dWt, PL * NG * IN_DIM / 4);
    prep_cvt<<<(PVT * HID / 4 + 255) / 256, 256>>>(W_y, dWHt, PVT * HID / 4);
    prep_cvt<<<(PET * HID / 4 + 255) / 256, 256>>>(W_E, dWHt + (size_t)PVT * HID,
                                                   PET * HID / 4);
    prep_A0<<<(PL * B_SZ * IN0 / 4 + 255) / 256, 256>>>(x, h_prev);

    const dim3 blk(256);
    // 1) gates for all 4 layers (K=1536); layer 0 fuses pointwise -> g_hidden
    gemm_tf32<0><<<dim3(NG / BN, B_SZ / BM, PL), blk, SMB>>>(c_prev, bg, 0);
    // 2) layers 1..3: tail split-K x4 (K=256 each) -> slices, then fused pointwise
    for (int l = 1; l < PL; l++) {
        gemm_tf32<1><<<dim3(NG / BN, B_SZ / BM, KS_TAIL), blk, SMB>>>(c_prev, bg, l);
        lstm_tail_pointwise<<<(B_SZ * PH) / 256, 256>>>(c_prev, l);
    }
    // 3) heads, split-K x8 (K=512 each) -> g_Gp scratch slices
    gemm_tf32<2><<<dim3(NHEAD / BN, B_SZ / BM, KS_HEAD), blk, SMB>>>(c_prev, bg, 0);
    // 4) reduce slices + bias -> d_out
    reduce_heads<<<(B_SZ * NHEAD / 4) / 256, 256>>>(b_y, b_E, out);
}

// round 13
// speedup vs baseline: 1.7872x; 1.1242x over previous
#include <cuda_runtime.h>
#include <cstdint>

#define B_SZ   512
#define PX     512
#define PH     1024
#define PL     4
#define PVT    512
#define PET    256
#define NG     4096      // 4 gates * PH (interleaved col space: col = 4h+g)
#define HID    4096      // PL * PH
#define IN_DIM 2560
#define IN0    1536      // PX + PH
#define NHEAD  768       // PVT + PET

#define BM 64
#define BN 128
#define BK 16
#define RS 20            // smem row stride (floats), conflict-free for frag LDS
#define KS_TAIL 4        // tail split-K factor (K=256 each)
#define KS_HEAD 8        // heads split-K factor (K=512 each)

// Scratch (no allocations allowed)
__device__ float g_Gp[PL * B_SZ * NG];        // MODE0 partials (interleaved) / head slices
__device__ float g_Tp[KS_TAIL * B_SZ * NG];   // tail split-K slices
__device__ float g_hidden[B_SZ * HID];        // concat hidden (tf32-rounded)
__device__ float g_A0[PL * B_SZ * IN0];       // tf32-rounded [x | h_prev[l]] per layer

__device__ __forceinline__ uint32_t cvt_tf32(float x) {
    uint32_t r; asm("cvt.rna.tf32.f32 %0, %1;" : "=r"(r) : "f"(x)); return r;
}
__device__ __forceinline__ float cvtf(float x) { return __uint_as_float(cvt_tf32(x)); }
__device__ __forceinline__ void cp16(uint32_t dst, const void* src) {
    asm volatile("cp.async.cg.shared.global [%0], [%1], 16;" :: "r"(dst), "l"(src));
}
__device__ __forceinline__ void mma_tf32(float (&d)[4], const uint32_t (&a)[4],
                                         uint32_t b0, uint32_t b1) {
    asm volatile(
        "mma.sync.aligned.m16n8k8.row.col.f32.tf32.tf32.f32 "
        "{%0,%1,%2,%3}, {%4,%5,%6,%7}, {%8,%9}, {%0,%1,%2,%3};\n"
        : "+f"(d[0]), "+f"(d[1]), "+f"(d[2]), "+f"(d[3])
        : "r"(a[0]), "r"(a[1]), "r"(a[2]), "r"(a[3]), "r"(b0), "r"(b1));
}
__device__ __forceinline__ float sigm(float x) { return 1.f / (1.f + __expf(-x)); }

// launch-time: build tf32-rounded [x | h_prev[l]] concat per layer
__global__ void prep_A0(const float* __restrict__ x, const float* __restrict__ h_prev) {
    const int i = blockIdx.x * blockDim.x + threadIdx.x;   // float4 index
    const int c  = (i * 4) % IN0;
    const int lb = (i * 4) / IN0;          // l * B_SZ + b
    const float4 v = (c < PX)
        ? *(const float4*)&x[(size_t)(lb % B_SZ) * PX + c]
        : *(const float4*)&h_prev[(size_t)lb * PH + (c - PX)];
    ((float4*)g_A0)[i] = make_float4(cvtf(v.x), cvtf(v.y), cvtf(v.z), cvtf(v.w));
}

// MODE 0: gates, all layers (grid.z=layer), K=1536. lz==0 -> fused pointwise -> g_hidden,
//         lz>0 -> +interleaved bias -> g_Gp.
// MODE 1: tail for `layer`, split-K (grid.z=kz in 0..3), K=256 each -> g_Tp slice.
// MODE 2: heads, split-K (grid.z=kz in 0..7), K=512 each -> g_Gp slice (scratch).
// Weights are consumed RAW (fp32 bits -> implicit tf32 truncation in HMMA).
template<int MODE>
__global__ void __launch_bounds__(256, 3)
gemm_tf32(const float* __restrict__ c_prev,
          const float* __restrict__ bg,
          const float* __restrict__ Wg,
          const float* __restrict__ W_y,
          const float* __restrict__ W_E,
          int layer)
{
    extern __shared__ float smem[];

    const int tid = threadIdx.x;
    const int bm  = blockIdx.y * BM;
    const int bn  = blockIdx.x * BN;
    const int lz  = (MODE == 0) ? blockIdx.z : layer;
    const int kz  = (MODE == 0) ? 0 : blockIdx.z;

    const int Ktot = (MODE == 0) ? IN0 : ((MODE == 1) ? PH / KS_TAIL : HID / KS_HEAD);
    const int nT = Ktot / BK;                 // 96 / 16 / 32

    // A loader: 64x16 floats -> 1 float4/thread
    const int lrowA = tid >> 2;               // 0..63
    const int kqA   = (tid & 3) * 4;          // 0,4,8,12
    // B loader: 128x16 floats -> 2 float4/thread
    const int lrowB = tid >> 1;               // 0..127
    const int kqB   = (tid & 1) * 8;          // 0,8

    const uint32_t sBase = (uint32_t)__cvta_generic_to_shared(smem);
    const uint32_t ldA = (uint32_t)(lrowA * RS + kqA) * 4u;
    const uint32_t ldB = (uint32_t)(lrowB * RS + kqB) * 4u;

    const int warp = tid >> 5;
    const int lane = tid & 31;
    const int grp  = lane >> 2;
    const int q    = lane & 3;
    const int wm   = (warp & 1) * 32;
    const int wn   = (warp >> 1) * 32;

    float acc[2][4][4];
    #pragma unroll
    for (int i = 0; i < 2; i++)
        #pragma unroll
        for (int j = 0; j < 4; j++)
            #pragma unroll
            for (int v = 0; v < 4; v++) acc[i][j][v] = 0.f;

    // interleaved weight row for gate GEMMs: col gn -> row (gn&3)*PH + (gn>>2)
    const int gn    = bn + lrowB;
    const int wrowI = (gn & 3) * PH + (gn >> 2);

    // invariant source row pointers
    const float* pa_row;
    const float* pb_row;
    if (MODE == 0) {
        pa_row = g_A0 + ((size_t)lz * B_SZ + bm + lrowA) * IN0;
        pb_row = Wg + ((size_t)lz * NG + wrowI) * IN_DIM;
    } else if (MODE == 1) {
        pa_row = g_hidden + (size_t)(bm + lrowA) * HID + (layer - 1) * PH
               + kz * (PH / KS_TAIL);
        pb_row = Wg + ((size_t)layer * NG + wrowI) * IN_DIM + IN0
               + kz * (PH / KS_TAIL);
    } else {
        pa_row = g_hidden + (size_t)(bm + lrowA) * HID + kz * (HID / KS_HEAD);
        pb_row = (gn < PVT) ? W_y + (size_t)gn * HID + kz * (HID / KS_HEAD)
                            : W_E + (size_t)(gn - PVT) * HID + kz * (HID / KS_HEAD);
    }

    auto load_stage = [&](int buf, int s) {
        const int gkA = s * BK + kqA;
        const uint32_t da = sBase + (uint32_t)buf * ((BM + BN) * RS * 4) + ldA;
        cp16(da, pa_row + gkA);
        const int gkB = s * BK + kqB;
        const uint32_t db = sBase + (uint32_t)buf * ((BM + BN) * RS * 4)
                          + (uint32_t)(BM * RS * 4) + ldB;
        cp16(db, pb_row + gkB); cp16(db + 16, pb_row + gkB + 4);
    };

    load_stage(0, 0);
    asm volatile("cp.async.commit_group;");
    load_stage(1, 1);
    asm volatile("cp.async.commit_group;");

    for (int s = 0; s < nT; s++) {
        const int buf = s % 3;
        if (s + 1 < nT) { asm volatile("cp.async.wait_group 1;"); }
        else            { asm volatile("cp.async.wait_group 0;"); }
        __syncthreads();                       // stage s visible; MMA(s-1) done everywhere
        if (s + 2 < nT) {
            load_stage((s + 2) % 3, s + 2);    // overwrites stage s-1's buffer (safe)
            asm volatile("cp.async.commit_group;");
        }

        const float* __restrict__ Ab = smem + buf * ((BM + BN) * RS);
        const float* __restrict__ Bb = Ab + BM * RS;
        #pragma unroll
        for (int kk = 0; kk < BK; kk += 8) {
            uint32_t a[2][4];
            #pragma unroll
            for (int im = 0; im < 2; im++) {
                const int r = wm + im * 16 + grp;
                a[im][0] = __float_as_uint(Ab[(r    ) * RS + kk + q    ]);
                a[im][1] = __float_as_uint(Ab[(r + 8) * RS + kk + q    ]);
                a[im][2] = __float_as_uint(Ab[(r    ) * RS + kk + q + 4]);
                a[im][3] = __float_as_uint(Ab[(r + 8) * RS + kk + q + 4]);
            }
            #pragma unroll
            for (int jn = 0; jn < 4; jn++) {
                const int n = wn + jn * 8 + grp;
                const uint32_t b0 = __float_as_uint(Bb[n * RS + kk + q    ]);
                const uint32_t b1 = __float_as_uint(Bb[n * RS + kk + q + 4]);
                mma_tf32(acc[0][jn], a[0], b0, b1);
                mma_tf32(acc[1][jn], a[1], b0, b1);
            }
        }
    }

    // ================= epilogues =================
    if (MODE == 0 && lz == 0) {
        // fused LSTM pointwise for layer 0 (full K in this CTA)
        __syncthreads();                       // all warps done with smem tiles
        float* st = smem;                      // 64 x 132 floats = 33792 B
        #pragma unroll
        for (int im = 0; im < 2; im++) {
            const int rl = wm + im * 16 + grp;
            #pragma unroll
            for (int jn = 0; jn < 4; jn++) {
                const int cl = wn + jn * 8 + 2 * q;
                *(float2*)&st[rl * 132 + cl]       = make_float2(acc[im][jn][0], acc[im][jn][1]);
                *(float2*)&st[(rl + 8) * 132 + cl] = make_float2(acc[im][jn][2], acc[im][jn][3]);
            }
        }
        __syncthreads();

        const int hc = tid & 31;
        const int h  = (bn >> 2) + hc;
        #pragma unroll 1
        for (int pass = 0; pass < 8; pass++) {
            const int row = pass * 8 + (tid >> 5);
            const int gb  = bm + row;
            float4 g = *(const float4*)&st[row * 132 + 4 * hc];
            g.x += bg[0 * PH + h];
            g.y += bg[1 * PH + h];
            g.z += bg[2 * PH + h];
            g.w += bg[3 * PH + h];
            const float ig = sigm(g.x);
            const float fg = sigm(g.y);
            const float og = sigm(g.z);
            const float sg = tanhf(g.w);
            const float cp = c_prev[(size_t)gb * PH + h];
            const float cn = fg * cp + ig * sg;
            g_hidden[(size_t)gb * HID + h] = cvtf(og * tanhf(cn));
        }
        return;
    }

    if (MODE == 0) {
        // lz > 0: partial + interleaved bias -> g_Gp
        #pragma unroll
        for (int jn = 0; jn < 4; jn++) {
            const int c0 = bn + wn + jn * 8 + 2 * q;
            const int h  = c0 >> 2;
            const int g0 = c0 & 3;
            const float b0 = bg[(size_t)lz * NG + g0 * PH + h];
            const float b1 = bg[(size_t)lz * NG + (g0 + 1) * PH + h];
            #pragma unroll
            for (int im = 0; im < 2; im++) {
                const int r0 = bm + wm + im * 16 + grp;
                *(float2*)&g_Gp[((size_t)lz * B_SZ + r0    ) * NG + c0]
                    = make_float2(acc[im][jn][0] + b0, acc[im][jn][1] + b1);
                *(float2*)&g_Gp[((size_t)lz * B_SZ + r0 + 8) * NG + c0]
                    = make_float2(acc[im][jn][2] + b0, acc[im][jn][3] + b1);
            }
        }
    } else if (MODE == 1) {
        float* sc = g_Tp + (size_t)kz * B_SZ * NG;
        #pragma unroll
        for (int im = 0; im < 2; im++) {
            const int r0 = bm + wm + im * 16 + grp;
            #pragma unroll
            for (int jn = 0; jn < 4; jn++) {
                const int c0 = bn + wn + jn * 8 + 2 * q;
                *(float2*)&sc[(size_t)(r0    ) * NG + c0]
                    = make_float2(acc[im][jn][0], acc[im][jn][1]);
                *(float2*)&sc[(size_t)(r0 + 8) * NG + c0]
                    = make_float2(acc[im][jn][2], acc[im][jn][3]);
            }
        }
    } else {
        float* sc = g_Gp + (size_t)kz * B_SZ * NHEAD;
        #pragma unroll
        for (int im = 0; im < 2; im++) {
            const int r0 = bm + wm + im * 16 + grp;
            #pragma unroll
            for (int jn = 0; jn < 4; jn++) {
                const int c0 = bn + wn + jn * 8 + 2 * q;
                *(float2*)&sc[(size_t)(r0    ) * NHEAD + c0]
                    = make_float2(acc[im][jn][0], acc[im][jn][1]);
                *(float2*)&sc[(size_t)(r0 + 8) * NHEAD + c0]
                    = make_float2(acc[im][jn][2], acc[im][jn][3]);
            }
        }
    }
}

// LSTM pointwise for layers 1..3: g = g_Gp[layer] (partial+bias) + 4 tail slices
__global__ void lstm_tail_pointwise(const float* __restrict__ c_prev, int layer) {
    const int idx = blockIdx.x * blockDim.x + threadIdx.x;   // one (b, h) each
    const int b = idx >> 10;
    const int h = idx & (PH - 1);
    const size_t off = (size_t)b * NG + 4 * h;
    float4 g = *(const float4*)&g_Gp[(size_t)layer * B_SZ * NG + off];
    #pragma unroll
    for (int kzi = 0; kzi < KS_TAIL; kzi++) {
        const float4 t = *(const float4*)&g_Tp[(size_t)kzi * B_SZ * NG + off];
        g.x += t.x; g.y += t.y; g.z += t.z; g.w += t.w;
    }
    const float ig = sigm(g.x);
    const float fg = sigm(g.y);
    const float og = sigm(g.z);
    const float sg = tanhf(g.w);
    const float cp = c_prev[((size_t)layer * B_SZ + b) * PH + h];
    const float cn = fg * cp + ig * sg;
    g_hidden[(size_t)b * HID + layer * PH + h] = cvtf(og * tanhf(cn));
}

// sum 8 head K-slices + bias -> split d_out layout
__global__ void reduce_heads(const float* __restrict__ b_y,
                             const float* __restrict__ b_E,
                             float* __restrict__ out)
{
    const int idx = (blockIdx.x * blockDim.x + threadIdx.x) * 4;
    const int r = idx / NHEAD;
    const int c = idx % NHEAD;
    float4 s = *(const float4*)&g_Gp[idx];
    #pragma unroll
    for (int kzi = 1; kzi < KS_HEAD; kzi++) {
        const float4 t = *(const float4*)&g_Gp[(size_t)kzi * B_SZ * NHEAD + idx];
        s.x += t.x; s.y += t.y; s.z += t.z; s.w += t.w;
    }
    if (c < PVT) {
        const float4 b = *(const float4*)&b_y[c];
        s.x += b.x; s.y += b.y; s.z += b.z; s.w += b.w;
        *(float4*)&out[(size_t)r * PVT + c] = s;
    } else {
        const int c2 = c - PVT;
        const float4 b = *(const float4*)&b_E[c2];
        s.x += b.x; s.y += b.y; s.z += b.z; s.w += b.w;
        *(float4*)&out[(size_t)B_SZ * PVT + (size_t)r * PET + c2] = s;
    }
}

extern "C" void kernel_launch(void* const* d_in, const int* in_sizes, int n_in,
                              void* d_out, int out_size) {
    const float* x      = (const float*)d_in[0];
    const float* h_prev = (const float*)d_in[1];
    const float* c_prev = (const float*)d_in[2];
    const float* Wg     = (const float*)d_in[3];
    const float* bg     = (const float*)d_in[4];
    const float* W_y    = (const float*)d_in[5];
    const float* b_y    = (const float*)d_in[6];
    const float* W_E    = (const float*)d_in[7];
    const float* b_E    = (const float*)d_in[8];
    float* out = (float*)d_out;

    const int SMB = 3 * (BM + BN) * RS * (int)sizeof(float);   // 46080 <= 48KB default
    const dim3 blk(256);

    // 0) tf32-rounded activation concat (weights consumed raw -> HW truncation)
    prep_A0<<<(PL * B_SZ * IN0 / 4 + 255) / 256, 256>>>(x, h_prev);

    // 1) gates for all 4 layers (K=1536); layer 0 fuses pointwise -> g_hidden
    gemm_tf32<0><<<dim3(NG / BN, B_SZ / BM, PL), blk, SMB>>>(
        c_prev, bg, Wg, W_y, W_E, 0);
    // 2) layers 1..3: tail split-K x4 (K=256 each) -> slices, then fused pointwise
    for (int l = 1; l < PL; l++) {
        gemm_tf32<1><<<dim3(NG / BN, B_SZ / BM, KS_TAIL), blk, SMB>>>(
            c_prev, bg, Wg, W_y, W_E, l);
        lstm_tail_pointwise<<<(B_SZ * PH) / 256, 256>>>(c_prev, l);
    }
    // 3) heads, split-K x8 (K=512 each) -> g_Gp scratch slices
    gemm_tf32<2><<<dim3(NHEAD / BN, B_SZ / BM, KS_HEAD), blk, SMB>>>(
        c_prev, bg, Wg, W_y, W_E, 0);
    // 4) reduce slices + bias -> d_out
    reduce_heads<<<(B_SZ * NHEAD / 4) / 256, 256>>>(b_y, b_E, out);
}